// round 13
// baseline (speedup 1.0000x reference)
#include <cuda_runtime.h>
#include <cstdint>

// ---------------- problem constants ----------------
constexpr int NAB  = 20000;
constexpr int NAG  = 20000;
constexpr int NTOT = NAB + NAG;      // 40000
constexpr int FF   = 256;
constexpr int EAB  = 320000;
constexpr int EAG  = 320000;
constexpr int ED   = 640000;
constexpr float EPS = 1e-5f;
constexpr float SLOPE = 0.2f;
constexpr float NINF = -3.0e38f;

// ---------------- scratch (device globals, no allocs) ----------------
__device__ float g_X[(size_t)NTOT * FF];
__device__ float g_A[(size_t)NTOT * FF];
__device__ float g_B[(size_t)NTOT * FF];
__device__ float g_dinv[NTOT];
__device__ float g_sc[2 * NTOT];            // hs | hd
__device__ float g_sumsq[2048];
__device__ float g_mu[1024], g_rstd[1024];

__device__ int g_degi[NTOT];
__device__ int g_cur[NTOT];
__device__ int g_off_g[NTOT + 1];
__device__ int g_off_d[NTOT + 1];
__device__ int g_csr_g[EAB + EAG];
__device__ int g_csr_d[ED];
__device__ int g_partials[64];

// ---------------- f32x2 helpers ----------------
typedef unsigned long long u64t;
__device__ __forceinline__ void fma2(u64t& d, u64t a, u64t b, u64t c) {
    asm("fma.rn.f32x2 %0, %1, %2, %3;" : "=l"(d) : "l"(a), "l"(b), "l"(c));
}
__device__ __forceinline__ void unpackf2(float& lo, float& hi, u64t v) {
    unsigned int l, h;
    asm("mov.b64 {%0, %1}, %2;" : "=r"(l), "=r"(h) : "l"(v));
    lo = __uint_as_float(l); hi = __uint_as_float(h);
}

__device__ __forceinline__ float lrelu(float x) { return x > 0.f ? x : SLOPE * x; }

// ---------------- tiny utility kernels ----------------
__global__ void k_filli(int* p, int v, int n) {
    int i = blockIdx.x * blockDim.x + threadIdx.x;
    if (i < n) p[i] = v;
}
__global__ void k_fill(float* p, float v, int n) {
    int i = blockIdx.x * blockDim.x + threadIdx.x;
    if (i < n) p[i] = v;
}
__global__ void k_copyi(const int* __restrict__ a, int* __restrict__ b, int n) {
    int i = blockIdx.x * blockDim.x + threadIdx.x;
    if (i < n) b[i] = a[i];
}
__global__ void k_deg(const int* __restrict__ dst, int E, int* __restrict__ deg) {
    int i = blockIdx.x * blockDim.x + threadIdx.x;
    if (i < E) atomicAdd(&deg[dst[i]], 1);
}
__global__ void k_dinv(const int* __restrict__ deg, float* __restrict__ dinv, int n) {
    int i = blockIdx.x * blockDim.x + threadIdx.x;
    if (i < n) dinv[i] = rsqrtf((float)deg[i] + 1.0f);
}

// ---------------- parallel exclusive scan ----------------
constexpr int SCAN_T = 256;
constexpr int SCAN_ITEMS = 4;
constexpr int SCAN_CHUNK = SCAN_T * SCAN_ITEMS;

__global__ void k_scan1(const int* __restrict__ deg, int n, int* __restrict__ partials) {
    __shared__ int sh[SCAN_T];
    int b = blockIdx.x, t = threadIdx.x;
    int base = b * SCAN_CHUNK + t * SCAN_ITEMS;
    int s = 0;
#pragma unroll
    for (int k = 0; k < SCAN_ITEMS; k++) { int i = base + k; if (i < n) s += deg[i]; }
    sh[t] = s;
    __syncthreads();
    for (int d = 128; d > 0; d >>= 1) {
        if (t < d) sh[t] += sh[t + d];
        __syncthreads();
    }
    if (t == 0) partials[b] = sh[0];
}

__global__ void k_scan2(int* __restrict__ partials, int nb, int* __restrict__ off, int n) {
    __shared__ int sh[64];
    int t = threadIdx.x;
    int v = (t < nb) ? partials[t] : 0;
    sh[t] = v;
    __syncthreads();
    for (int d = 1; d < 64; d <<= 1) {
        int u = (t >= d) ? sh[t - d] : 0;
        __syncthreads();
        sh[t] += u;
        __syncthreads();
    }
    if (t < nb) partials[t] = sh[t] - v;
    if (t == 0) off[n] = sh[63];
}

__global__ void k_scan3(const int* __restrict__ deg, int n,
                        const int* __restrict__ partials, int* __restrict__ off) {
    __shared__ int sh[SCAN_T];
    int b = blockIdx.x, t = threadIdx.x;
    int base = b * SCAN_CHUNK + t * SCAN_ITEMS;
    int v[SCAN_ITEMS];
    int s = 0;
#pragma unroll
    for (int k = 0; k < SCAN_ITEMS; k++) { int i = base + k; v[k] = (i < n) ? deg[i] : 0; s += v[k]; }
    sh[t] = s;
    __syncthreads();
    for (int d = 1; d < SCAN_T; d <<= 1) {
        int u = (t >= d) ? sh[t - d] : 0;
        __syncthreads();
        sh[t] += u;
        __syncthreads();
    }
    int run = partials[b] + sh[t] - s;
#pragma unroll
    for (int k = 0; k < SCAN_ITEMS; k++) {
        int i = base + k;
        if (i < n) { off[i] = run; run += v[k]; }
    }
}

__global__ void k_scatter(const int* __restrict__ src, const int* __restrict__ dst, int E,
                          int* __restrict__ cur, int* __restrict__ csr,
                          int dstbase, int srcbase) {
    int i = blockIdx.x * blockDim.x + threadIdx.x;
    if (i >= E) return;
    int pos = atomicAdd(&cur[dst[i] + dstbase], 1);
    csr[pos] = src[i] + srcbase;
}

// ---------------- f32x2 SGEMM v2: 128 threads, tile 128Mx128N, TM=16(M-pairs) x TN=8 ----------------
// As[k][m] (k-major), Bs[k][2n] duplicated (w,w) -> LDS.128 gives f32x2 operands with 0 MOVs.
// SCORES: hs[r]+=C_row.a_s, hd[r]+=C_row.a_d
__device__ __forceinline__ void gemm2_load(
    const float* __restrict__ A, const float* __restrict__ W, int M,
    int m0, int n0, int k0, int relu,
    float (*As)[128], float (*Bs)[256], int tid)
{
    // A: thread t -> row m0+t, cols k0..k0+16 (4x float4), store transposed As[k][t]
    {
        int r = m0 + tid;
        int rc = r < M ? r : M - 1;
        const float4* ap = (const float4*)(A + (size_t)rc * FF + k0);
#pragma unroll
        for (int i = 0; i < 4; i++) {
            float4 v = ap[i];
            if (relu) {
                v.x = fmaxf(v.x, 0.f); v.y = fmaxf(v.y, 0.f);
                v.z = fmaxf(v.z, 0.f); v.w = fmaxf(v.w, 0.f);
            }
            As[i * 4 + 0][tid] = v.x;
            As[i * 4 + 1][tid] = v.y;
            As[i * 4 + 2][tid] = v.z;
            As[i * 4 + 3][tid] = v.w;
        }
    }
    // B: thread t -> k-row kr = t>>3, cols n0 + (t&7)*16 .. +16, store duplicated
    {
        int kr = tid >> 3;
        int ng = (tid & 7) * 16;
        const float4* wp = (const float4*)(W + (size_t)(k0 + kr) * FF + n0 + ng);
#pragma unroll
        for (int i = 0; i < 4; i++) {
            float4 v = wp[i];
            *(float4*)&Bs[kr][2 * (ng + i * 4)]     = make_float4(v.x, v.x, v.y, v.y);
            *(float4*)&Bs[kr][2 * (ng + i * 4) + 4] = make_float4(v.z, v.z, v.w, v.w);
        }
    }
}

template<bool SCORES>
__global__ void __launch_bounds__(128) k_gemm2(const float* __restrict__ A,
                                               const float* __restrict__ W,
                                               float* __restrict__ C, int M,
                                               const float* __restrict__ a_s,
                                               const float* __restrict__ a_d,
                                               float* __restrict__ hs,
                                               float* __restrict__ hd,
                                               int relu) {
    __shared__ float As[2][16][128];
    __shared__ float Bs[2][16][256];
    const int tid = threadIdx.x;
    const int m0 = blockIdx.x * 128;
    const int n0 = blockIdx.y * 128;
    const int tx = tid & 15, ty = tid >> 4;    // tx: 16 n-groups of 8; ty: 8 m-groups of 16

    u64t acc[8][8];                             // [m-pair 0..7][n 0..7]
#pragma unroll
    for (int p = 0; p < 8; p++)
#pragma unroll
        for (int j = 0; j < 8; j++) acc[p][j] = 0ull;

    gemm2_load(A, W, M, m0, n0, 0, relu, As[0], Bs[0], tid);
    __syncthreads();

    int buf = 0;
    for (int k0 = 0; k0 < 256; k0 += 16) {
        if (k0 < 240)
            gemm2_load(A, W, M, m0, n0, k0 + 16, relu, As[buf ^ 1], Bs[buf ^ 1], tid);
#pragma unroll
        for (int kk = 0; kk < 16; kk++) {
            union { uint4 q[4]; u64t u[8]; } a, b;
            a.q[0] = *(const uint4*)&As[buf][kk][ty * 16];
            a.q[1] = *(const uint4*)&As[buf][kk][ty * 16 + 4];
            a.q[2] = *(const uint4*)&As[buf][kk][ty * 16 + 8];
            a.q[3] = *(const uint4*)&As[buf][kk][ty * 16 + 12];
            b.q[0] = *(const uint4*)&Bs[buf][kk][tx * 16];
            b.q[1] = *(const uint4*)&Bs[buf][kk][tx * 16 + 4];
            b.q[2] = *(const uint4*)&Bs[buf][kk][tx * 16 + 8];
            b.q[3] = *(const uint4*)&Bs[buf][kk][tx * 16 + 12];
#pragma unroll
            for (int p = 0; p < 8; p++)
#pragma unroll
                for (int j = 0; j < 8; j++) fma2(acc[p][j], a.u[p], b.u[j], acc[p][j]);
        }
        __syncthreads();
        buf ^= 1;
    }

    float as0[8], ad0[8];
    if (SCORES) {
#pragma unroll
        for (int j = 0; j < 8; j++) {
            as0[j] = __ldg(a_s + n0 + tx * 8 + j);
            ad0[j] = __ldg(a_d + n0 + tx * 8 + j);
        }
    }

#pragma unroll
    for (int p = 0; p < 8; p++) {
        int r0 = m0 + ty * 16 + 2 * p;
        float lo[8], hi[8];
#pragma unroll
        for (int j = 0; j < 8; j++) unpackf2(lo[j], hi[j], acc[p][j]);
        if (r0 < M) {
            *(float4*)(C + (size_t)r0 * FF + n0 + tx * 8)     = make_float4(lo[0], lo[1], lo[2], lo[3]);
            *(float4*)(C + (size_t)r0 * FF + n0 + tx * 8 + 4) = make_float4(lo[4], lo[5], lo[6], lo[7]);
        }
        if (r0 + 1 < M) {
            *(float4*)(C + (size_t)(r0 + 1) * FF + n0 + tx * 8)     = make_float4(hi[0], hi[1], hi[2], hi[3]);
            *(float4*)(C + (size_t)(r0 + 1) * FF + n0 + tx * 8 + 4) = make_float4(hi[4], hi[5], hi[6], hi[7]);
        }
        if (SCORES) {
            float s0 = 0.f, d0 = 0.f, s1 = 0.f, d1 = 0.f;
#pragma unroll
            for (int j = 0; j < 8; j++) {
                s0 += lo[j] * as0[j]; d0 += lo[j] * ad0[j];
                s1 += hi[j] * as0[j]; d1 += hi[j] * ad0[j];
            }
#pragma unroll
            for (int o = 8; o > 0; o >>= 1) {
                s0 += __shfl_xor_sync(0xffffffffu, s0, o);
                d0 += __shfl_xor_sync(0xffffffffu, d0, o);
                s1 += __shfl_xor_sync(0xffffffffu, s1, o);
                d1 += __shfl_xor_sync(0xffffffffu, d1, o);
            }
            if (tx == 0) {
                if (r0 < M)     { atomicAdd(hs + r0, s0);     atomicAdd(hd + r0, d0); }
                if (r0 + 1 < M) { atomicAdd(hs + r0 + 1, s1); atomicAdd(hd + r0 + 1, d1); }
            }
        }
    }
}

// ---------------- GCN gather: warp per node (combined graph) ----------------
__global__ void k_gcn_gather(const int* __restrict__ off, const int* __restrict__ csr,
                             const float* __restrict__ h, float* __restrict__ out,
                             const float* __restrict__ dinv,
                             const float* __restrict__ bab, const float* __restrict__ bag,
                             int n, int nsplit) {
    int w = (blockIdx.x * blockDim.x + threadIdx.x) >> 5;
    int lane = threadIdx.x & 31;
    if (w >= n) return;
    int e0 = off[w], e1 = off[w + 1];
    float dv = dinv[w];
    float4 a0 = make_float4(0.f, 0.f, 0.f, 0.f);
    float4 a1 = make_float4(0.f, 0.f, 0.f, 0.f);
    for (int base = e0; base < e1; base += 32) {
        int e = base + lane;
        int idx = (e < e1) ? csr[e] : 0;
        float wv = (e < e1) ? dinv[idx] : 0.f;
        int cnt = min(32, e1 - base);
        for (int k = 0; k < cnt; k++) {
            int s = __shfl_sync(0xffffffffu, idx, k);
            float ws = __shfl_sync(0xffffffffu, wv, k);
            const float4* hp = (const float4*)(h + (size_t)s * FF) + lane;
            float4 v0 = hp[0];
            float4 v1 = hp[32];
            a0.x += v0.x * ws; a0.y += v0.y * ws; a0.z += v0.z * ws; a0.w += v0.w * ws;
            a1.x += v1.x * ws; a1.y += v1.y * ws; a1.z += v1.z * ws; a1.w += v1.w * ws;
        }
    }
    {
        const float4* hp = (const float4*)(h + (size_t)w * FF) + lane;
        float4 v0 = hp[0], v1 = hp[32];
        a0.x += v0.x * dv; a0.y += v0.y * dv; a0.z += v0.z * dv; a0.w += v0.w * dv;
        a1.x += v1.x * dv; a1.y += v1.y * dv; a1.z += v1.z * dv; a1.w += v1.w * dv;
    }
    const float* b = (w < nsplit) ? bab : bag;
    float4 b0 = *((const float4*)b + lane);
    float4 b1 = *((const float4*)b + lane + 32);
    float4 o0 = make_float4(a0.x * dv + b0.x, a0.y * dv + b0.y, a0.z * dv + b0.z, a0.w * dv + b0.w);
    float4 o1 = make_float4(a1.x * dv + b1.x, a1.y * dv + b1.y, a1.z * dv + b1.z, a1.w * dv + b1.w);
    float4* op = (float4*)(out + (size_t)w * FF) + lane;
    op[0] = o0;
    op[32] = o1;
}

// ---------------- BN ----------------
__global__ void k_stats4(const float* __restrict__ p0, const float* __restrict__ p1,
                         const float* __restrict__ p2, const float* __restrict__ p3,
                         int nrows, float* __restrict__ sum, float* __restrict__ sq) {
    int seg = blockIdx.y;
    const float* X = (seg == 0) ? p0 : (seg == 1) ? p1 : (seg == 2) ? p2 : p3;
    int c = threadIdx.x;
    float s = 0.f, q = 0.f;
    for (int r = blockIdx.x; r < nrows; r += gridDim.x) {
        float v = X[(size_t)r * FF + c];
        s += v; q += v * v;
    }
    atomicAdd(&sum[seg * 256 + c], s);
    atomicAdd(&sq[seg * 256 + c], q);
}

__global__ void k_finalize(const float* __restrict__ sum, const float* __restrict__ sq,
                           float* __restrict__ mu, float* __restrict__ rstd, int n, int cnt) {
    int i = blockIdx.x * blockDim.x + threadIdx.x;
    if (i >= cnt) return;
    float m = sum[i] / n;
    mu[i] = m;
    rstd[i] = rsqrtf(sq[i] / n - m * m + EPS);
}

__global__ void k_bnrelu2(const float* __restrict__ X, float* __restrict__ Y,
                          const float* __restrict__ mu, const float* __restrict__ rstd,
                          const float* __restrict__ ga, const float* __restrict__ ba,
                          const float* __restrict__ gb, const float* __restrict__ bb,
                          int n, int nsplit) {
    size_t idx = (size_t)blockIdx.x * blockDim.x + threadIdx.x;
    if (idx >= (size_t)n * FF) return;
    int node = (int)(idx >> 8), c = (int)(idx & 255);
    bool lo = node < nsplit;
    int mc = lo ? c : c + 256;
    const float* g = lo ? ga : gb;
    const float* b = lo ? ba : bb;
    float v = (X[idx] - mu[mc]) * rstd[mc] * g[c] + b[c];
    Y[idx] = fmaxf(v, 0.f);
}

// ---------------- fused GAT per node ----------------
__global__ void k_gat_node(const int* __restrict__ off, const int* __restrict__ csr,
                           const float* __restrict__ h, float* __restrict__ out,
                           const float* __restrict__ hs, const float* __restrict__ hd,
                           const float* __restrict__ b, int n) {
    int w = (blockIdx.x * blockDim.x + threadIdx.x) >> 5;
    int lane = threadIdx.x & 31;
    if (w >= n) return;
    int e0 = off[w], e1 = off[w + 1];
    float hdn = hd[w];
    float self_e = lrelu(hs[w] + hdn);

    float m = (lane == 0) ? self_e : NINF;
    float s = (lane == 0) ? 1.f : 0.f;
    for (int e = e0 + lane; e < e1; e += 32) {
        float v = lrelu(hs[csr[e]] + hdn);
        if (v > m) { s = s * __expf(m - v) + 1.f; m = v; }
        else       { s += __expf(v - m); }
    }
#pragma unroll
    for (int o = 16; o > 0; o >>= 1) {
        float mo = __shfl_xor_sync(0xffffffffu, m, o);
        float so = __shfl_xor_sync(0xffffffffu, s, o);
        float mn = fmaxf(m, mo);
        s = s * __expf(m - mn) + so * __expf(mo - mn);
        m = mn;
    }
    float inv = 1.f / s;

    float4 a0, a1;
    {
        float sa = __expf(self_e - m) * inv;
        const float4* hp = (const float4*)(h + (size_t)w * FF) + lane;
        float4 v0 = hp[0], v1 = hp[32];
        a0 = make_float4(v0.x * sa, v0.y * sa, v0.z * sa, v0.w * sa);
        a1 = make_float4(v1.x * sa, v1.y * sa, v1.z * sa, v1.w * sa);
    }
    for (int base = e0; base < e1; base += 32) {
        int e = base + lane;
        int idx = (e < e1) ? csr[e] : 0;
        float al = 0.f;
        if (e < e1) al = __expf(lrelu(hs[idx] + hdn) - m) * inv;
        int cnt = min(32, e1 - base);
        for (int k = 0; k < cnt; k++) {
            int sn = __shfl_sync(0xffffffffu, idx, k);
            float av = __shfl_sync(0xffffffffu, al, k);
            const float4* hp = (const float4*)(h + (size_t)sn * FF) + lane;
            float4 v0 = hp[0];
            float4 v1 = hp[32];
            a0.x += v0.x * av; a0.y += v0.y * av; a0.z += v0.z * av; a0.w += v0.w * av;
            a1.x += v1.x * av; a1.y += v1.y * av; a1.z += v1.z * av; a1.w += v1.w * av;
        }
    }
    float4 b0 = *((const float4*)b + lane);
    float4 b1 = *((const float4*)b + lane + 32);
    a0.x += b0.x; a0.y += b0.y; a0.z += b0.z; a0.w += b0.w;
    a1.x += b1.x; a1.y += b1.y; a1.z += b1.z; a1.w += b1.w;
    float4* op = (float4*)(out + (size_t)w * FF) + lane;
    op[0] = a0;
    op[32] = a1;
}

// ---------------- final: relu(bn(concat[X,H])) @ Wfc + bfc ----------------
__global__ void k_final(const float* __restrict__ Xp, const float* __restrict__ Hp,
                        const float* __restrict__ mu, const float* __restrict__ rstd,
                        const float* __restrict__ g, const float* __restrict__ b,
                        const float* __restrict__ Wfc, const float* __restrict__ bfc,
                        float* __restrict__ out, int n) {
    int w = (blockIdx.x * blockDim.x + threadIdx.x) >> 5;
    int lane = threadIdx.x & 31;
    if (w >= n) return;
    float acc = 0.f;
#pragma unroll
    for (int j = 0; j < 16; j++) {
        int c = j * 32 + lane;
        float v = (c < FF) ? Xp[(size_t)w * FF + c] : Hp[(size_t)w * FF + (c - FF)];
        v = (v - mu[c]) * rstd[c] * g[c] + b[c];
        v = fmaxf(v, 0.f);
        acc += v * __ldg(Wfc + c);
    }
#pragma unroll
    for (int off = 16; off > 0; off >>= 1) acc += __shfl_down_sync(0xffffffffu, acc, off);
    if (lane == 0) out[w] = acc + bfc[0];
}

// ---------------- host orchestration ----------------
extern "C" void kernel_launch(void* const* d_in, const int* in_sizes, int n_in,
                              void* d_out, int out_size) {
    const float* x_ab   = (const float*)d_in[0];
    const float* x_ag   = (const float*)d_in[1];
    const float* W_gcn  = (const float*)d_in[2];
    const float* b_gcn  = (const float*)d_in[3];
    const float* g1     = (const float*)d_in[4];
    const float* be1    = (const float*)d_in[5];
    const float* W_aggcn= (const float*)d_in[6];
    const float* b_aggcn= (const float*)d_in[7];
    const float* ag_g1  = (const float*)d_in[8];
    const float* ag_be1 = (const float*)d_in[9];
    const float* W_gat  = (const float*)d_in[10];
    const float* a_src  = (const float*)d_in[11];
    const float* a_dst  = (const float*)d_in[12];
    const float* b_gat  = (const float*)d_in[13];
    const float* W_gat2 = (const float*)d_in[14];
    const float* a_src2 = (const float*)d_in[15];
    const float* a_dst2 = (const float*)d_in[16];
    const float* b_gat2 = (const float*)d_in[17];
    const float* ag_g2  = (const float*)d_in[18];
    const float* ag_be2 = (const float*)d_in[19];
    const float* W_agfc = (const float*)d_in[20];
    const float* b_agfc = (const float*)d_in[21];
    const float* g2     = (const float*)d_in[22];
    const float* be2    = (const float*)d_in[23];
    const float* W_fc   = (const float*)d_in[24];
    const float* b_fc   = (const float*)d_in[25];
    const int* e_ab     = (const int*)d_in[26];
    const int* e_ag     = (const int*)d_in[27];
    const int* e_d      = (const int*)d_in[28];
    float* out = (float*)d_out;

    float *pX, *pA, *pB, *pdinv, *psc, *pss, *pmu, *prstd;
    int *pdegi, *pcur, *poff_g, *poff_d, *pcsr_g, *pcsr_d, *ppart;
    cudaGetSymbolAddress((void**)&pX, g_X);
    cudaGetSymbolAddress((void**)&pA, g_A);
    cudaGetSymbolAddress((void**)&pB, g_B);
    cudaGetSymbolAddress((void**)&pdinv, g_dinv);
    cudaGetSymbolAddress((void**)&psc, g_sc);
    cudaGetSymbolAddress((void**)&pss, g_sumsq);
    cudaGetSymbolAddress((void**)&pmu, g_mu);
    cudaGetSymbolAddress((void**)&prstd, g_rstd);
    cudaGetSymbolAddress((void**)&pdegi, g_degi);
    cudaGetSymbolAddress((void**)&pcur, g_cur);
    cudaGetSymbolAddress((void**)&poff_g, g_off_g);
    cudaGetSymbolAddress((void**)&poff_d, g_off_d);
    cudaGetSymbolAddress((void**)&pcsr_g, g_csr_g);
    cudaGetSymbolAddress((void**)&pcsr_d, g_csr_d);
    cudaGetSymbolAddress((void**)&ppart, g_partials);
    float* psum = pss;
    float* psq  = pss + 1024;

    const int* eab_src = e_ab;           const int* eab_dst = e_ab + EAB;
    const int* eag_src = e_ag;           const int* eag_dst = e_ag + EAG;
    const int* ed_src  = e_d;            const int* ed_dst  = e_d + ED;

    const int NB_TOT = (NTOT + SCAN_CHUNK - 1) / SCAN_CHUNK;
    const dim3 GAB((NAB + 127) / 128, 2);
    const dim3 GT((NTOT + 127) / 128, 2);

    // ---- launches 0-2: degree ----
    k_filli<<<(NTOT + 255) / 256, 256>>>(pdegi, 0, NTOT);                       // 0
    k_deg<<<(EAB + 255) / 256, 256>>>(eab_dst, EAB, pdegi);                     // 1
    k_deg<<<(EAG + 255) / 256, 256>>>(eag_dst, EAG, pdegi + NAB);               // 2
    // ---- launch 3: first GEMM (profiled) ----
    k_gemm2<false><<<GAB, 128>>>(x_ab, W_gcn, pB, NAB,
                                 nullptr, nullptr, nullptr, nullptr, 0);        // 3
    k_gemm2<false><<<GAB, 128>>>(x_ag, W_aggcn, pB + (size_t)NAB * FF, NAB,
                                 nullptr, nullptr, nullptr, nullptr, 0);        // 4
    k_dinv<<<(NTOT + 255) / 256, 256>>>(pdegi, pdinv, NTOT);

    // ---- combined GCN CSR over NTOT ----
    k_scan1<<<NB_TOT, SCAN_T>>>(pdegi, NTOT, ppart);
    k_scan2<<<1, 64>>>(ppart, NB_TOT, poff_g, NTOT);
    k_scan3<<<NB_TOT, SCAN_T>>>(pdegi, NTOT, ppart, poff_g);
    k_copyi<<<(NTOT + 255) / 256, 256>>>(poff_g, pcur, NTOT);
    k_scatter<<<(EAB + 255) / 256, 256>>>(eab_src, eab_dst, EAB, pcur, pcsr_g, 0, 0);
    k_scatter<<<(EAG + 255) / 256, 256>>>(eag_src, eag_dst, EAG, pcur, pcsr_g, NAB, NAB);

    // ---- GCN aggregate (gather) into g_A ----
    k_gcn_gather<<<(NTOT * 32 + 255) / 256, 256>>>(poff_g, pcsr_g, pB, pA, pdinv,
                                                   b_gcn, b_aggcn, NTOT, NAB);

    // ---- CSR build: d graph ----
    k_filli<<<(NTOT + 255) / 256, 256>>>(pdegi, 0, NTOT);
    k_deg<<<(ED + 255) / 256, 256>>>(ed_dst, ED, pdegi);
    k_scan1<<<NB_TOT, SCAN_T>>>(pdegi, NTOT, ppart);
    k_scan2<<<1, 64>>>(ppart, NB_TOT, poff_d, NTOT);
    k_scan3<<<NB_TOT, SCAN_T>>>(pdegi, NTOT, ppart, poff_d);
    k_copyi<<<(NTOT + 255) / 256, 256>>>(poff_d, pcur, NTOT);
    k_scatter<<<(ED + 255) / 256, 256>>>(ed_src, ed_dst, ED, pcur, pcsr_d, 0, 0);

    // ---- BN1 + relu -> g_X ----
    k_fill<<<8, 256>>>(pss, 0.f, 2048);
    {
        dim3 gs(96, 2);
        k_stats4<<<gs, 256>>>(pA, pA + (size_t)NAB * FF, nullptr, nullptr, NAB, psum, psq);
    }
    k_finalize<<<2, 256>>>(psum, psq, pmu, prstd, NAB, 512);
    k_bnrelu2<<<((size_t)NTOT * FF + 255) / 256, 256>>>(pA, pX, pmu, prstd,
                                                        g1, be1, ag_g1, ag_be1, NTOT, NAB);

    // ---- GAT1: g_X -> g_A ----
    k_fill<<<(2 * NTOT + 255) / 256, 256>>>(psc, 0.f, 2 * NTOT);
    k_gemm2<true><<<GT, 128>>>(pX, W_gat, pB, NTOT, a_src, a_dst, psc, psc + NTOT, 0);
    k_gat_node<<<(NTOT * 32 + 255) / 256, 256>>>(poff_d, pcsr_d, pB, pA,
                                                 psc, psc + NTOT, b_gat, NTOT);

    // ---- GAT2: relu(g_A) -> g_A ----
    k_fill<<<(2 * NTOT + 255) / 256, 256>>>(psc, 0.f, 2 * NTOT);
    k_gemm2<true><<<GT, 128>>>(pA, W_gat2, pB, NTOT, a_src2, a_dst2, psc, psc + NTOT, 1);
    k_gat_node<<<(NTOT * 32 + 255) / 256, 256>>>(poff_d, pcsr_d, pB, pA,
                                                 psc, psc + NTOT, b_gat2, NTOT);

    // ---- final BN stats over concat halves ----
    k_fill<<<8, 256>>>(pss, 0.f, 2048);
    {
        dim3 gs(96, 4);
        k_stats4<<<gs, 256>>>(pA, pX, pA + (size_t)NAB * FF, pX + (size_t)NAB * FF,
                              NAB, psum, psq);
    }
    k_finalize<<<4, 256>>>(psum, psq, pmu, prstd, NAB, 1024);

    // ---- final outputs ----
    k_final<<<(NAB * 32 + 255) / 256, 256>>>(pA, pX, pmu, prstd, g2, be2, W_fc, b_fc,
                                             out, NAB);
    k_final<<<(NAG * 32 + 255) / 256, 256>>>(pA + (size_t)NAB * FF, pX + (size_t)NAB * FF,
                                             pmu + 512, prstd + 512, ag_g2, ag_be2,
                                             W_agfc, b_agfc, out + NAB, NAG);
}

// round 14
// speedup vs baseline: 1.7129x; 1.7129x over previous
#include <cuda_runtime.h>
#include <cstdint>

// ---------------- problem constants ----------------
constexpr int NAB  = 20000;
constexpr int NAG  = 20000;
constexpr int NTOT = NAB + NAG;      // 40000
constexpr int FF   = 256;
constexpr int EAB  = 320000;
constexpr int EAG  = 320000;
constexpr int ED   = 640000;
constexpr float EPS = 1e-5f;
constexpr float SLOPE = 0.2f;
constexpr float NINF = -3.0e38f;

// ---------------- scratch (device globals, no allocs) ----------------
__device__ float g_X[(size_t)NTOT * FF];
__device__ float g_A[(size_t)NTOT * FF];
__device__ float g_B[(size_t)NTOT * FF];
__device__ float g_dinv[NTOT];
__device__ float g_sc[2 * NTOT];            // hs | hd
__device__ float g_sumsq[2048];
__device__ float g_mu[1024], g_rstd[1024];

__device__ int g_degi[NTOT];
__device__ int g_cur[NTOT];
__device__ int g_off_g[NTOT + 1];
__device__ int g_off_d[NTOT + 1];
__device__ int g_csr_g[EAB + EAG];
__device__ int g_csr_d[ED];
__device__ int g_partials[64];

// ---------------- f32x2 helpers (sm_103a packed fp32 FMA) ----------------
typedef unsigned long long u64t;
__device__ __forceinline__ void fma2(u64t& d, u64t a, u64t b, u64t c) {
    asm("fma.rn.f32x2 %0, %1, %2, %3;" : "=l"(d) : "l"(a), "l"(b), "l"(c));
}
__device__ __forceinline__ u64t packf2(float lo, float hi) {
    u64t d;
    asm("mov.b64 %0, {%1, %2};" : "=l"(d) : "r"(__float_as_uint(lo)), "r"(__float_as_uint(hi)));
    return d;
}
__device__ __forceinline__ void unpackf2(float& lo, float& hi, u64t v) {
    unsigned int l, h;
    asm("mov.b64 {%0, %1}, %2;" : "=r"(l), "=r"(h) : "l"(v));
    lo = __uint_as_float(l); hi = __uint_as_float(h);
}

__device__ __forceinline__ float lrelu(float x) { return x > 0.f ? x : SLOPE * x; }

// ---------------- tiny utility kernels ----------------
__global__ void k_filli(int* p, int v, int n) {
    int i = blockIdx.x * blockDim.x + threadIdx.x;
    if (i < n) p[i] = v;
}
__global__ void k_fill(float* p, float v, int n) {
    int i = blockIdx.x * blockDim.x + threadIdx.x;
    if (i < n) p[i] = v;
}
__global__ void k_deg(const int* __restrict__ dst, int E, int* __restrict__ deg) {
    int i = blockIdx.x * blockDim.x + threadIdx.x;
    if (i < E) atomicAdd(&deg[dst[i]], 1);
}
__global__ void k_dinv(const int* __restrict__ deg, float* __restrict__ dinv, int n) {
    int i = blockIdx.x * blockDim.x + threadIdx.x;
    if (i < n) dinv[i] = rsqrtf((float)deg[i] + 1.0f);
}

// ---------------- parallel exclusive scan (3 kernels) ----------------
constexpr int SCAN_T = 256;
constexpr int SCAN_ITEMS = 4;
constexpr int SCAN_CHUNK = SCAN_T * SCAN_ITEMS;   // 1024

__global__ void k_scan1(const int* __restrict__ deg, int n, int* __restrict__ partials) {
    __shared__ int sh[SCAN_T];
    int b = blockIdx.x, t = threadIdx.x;
    int base = b * SCAN_CHUNK + t * SCAN_ITEMS;
    int s = 0;
#pragma unroll
    for (int k = 0; k < SCAN_ITEMS; k++) { int i = base + k; if (i < n) s += deg[i]; }
    sh[t] = s;
    __syncthreads();
    for (int d = 128; d > 0; d >>= 1) {
        if (t < d) sh[t] += sh[t + d];
        __syncthreads();
    }
    if (t == 0) partials[b] = sh[0];
}

__global__ void k_scan2(int* __restrict__ partials, int nb, int* __restrict__ off, int n) {
    __shared__ int sh[64];
    int t = threadIdx.x;
    int v = (t < nb) ? partials[t] : 0;
    sh[t] = v;
    __syncthreads();
    for (int d = 1; d < 64; d <<= 1) {
        int u = (t >= d) ? sh[t - d] : 0;
        __syncthreads();
        sh[t] += u;
        __syncthreads();
    }
    if (t < nb) partials[t] = sh[t] - v;    // exclusive prefix
    if (t == 0) off[n] = sh[63];            // grand total
}

// writes BOTH off[] and cur[] (cur = working copy for the scatter pass)
__global__ void k_scan3(const int* __restrict__ deg, int n,
                        const int* __restrict__ partials, int* __restrict__ off,
                        int* __restrict__ cur) {
    __shared__ int sh[SCAN_T];
    int b = blockIdx.x, t = threadIdx.x;
    int base = b * SCAN_CHUNK + t * SCAN_ITEMS;
    int v[SCAN_ITEMS];
    int s = 0;
#pragma unroll
    for (int k = 0; k < SCAN_ITEMS; k++) { int i = base + k; v[k] = (i < n) ? deg[i] : 0; s += v[k]; }
    sh[t] = s;
    __syncthreads();
    for (int d = 1; d < SCAN_T; d <<= 1) {
        int u = (t >= d) ? sh[t - d] : 0;
        __syncthreads();
        sh[t] += u;
        __syncthreads();
    }
    int run = partials[b] + sh[t] - s;
#pragma unroll
    for (int k = 0; k < SCAN_ITEMS; k++) {
        int i = base + k;
        if (i < n) { off[i] = run; cur[i] = run; run += v[k]; }
    }
}

__global__ void k_scatter(const int* __restrict__ src, const int* __restrict__ dst, int E,
                          int* __restrict__ cur, int* __restrict__ csr,
                          int dstbase, int srcbase) {
    int i = blockIdx.x * blockDim.x + threadIdx.x;
    if (i >= E) return;
    int pos = atomicAdd(&cur[dst[i] + dstbase], 1);
    csr[pos] = src[i] + srcbase;
}

// ---------------- f32x2 SGEMM (round-8 double-buffered version, verbatim) ----------------
__device__ __forceinline__ void gemm_load_tile(
    const float* __restrict__ A, const float* __restrict__ W, int M,
    int m0, int n0, int k0, bool relu,
    float (*As)[128], float (*Bs)[128], int tid)
{
    const int arow = tid >> 2;
    const int acol = (tid & 3) * 4;
    const int brow = tid >> 5;
    const int bcol = (tid & 31) * 4;
#pragma unroll
    for (int i = 0; i < 2; i++) {
        int r = m0 + arow + i * 64;
        int rc = r < M ? r : M - 1;
        float4 v = *(const float4*)(A + (size_t)rc * FF + k0 + acol);
        if (relu) {
            v.x = fmaxf(v.x, 0.f); v.y = fmaxf(v.y, 0.f);
            v.z = fmaxf(v.z, 0.f); v.w = fmaxf(v.w, 0.f);
        }
        As[acol + 0][arow + i * 64] = v.x;
        As[acol + 1][arow + i * 64] = v.y;
        As[acol + 2][arow + i * 64] = v.z;
        As[acol + 3][arow + i * 64] = v.w;
    }
#pragma unroll
    for (int i = 0; i < 2; i++) {
        int kr = brow + i * 8;
        float4 v = *(const float4*)(W + (size_t)(k0 + kr) * FF + n0 + bcol);
        *(float4*)&Bs[kr][bcol] = v;
    }
}

template<bool RELU, bool SCORES>
__global__ void __launch_bounds__(256) k_gemm256(const float* __restrict__ A,
                                                 const float* __restrict__ W,
                                                 float* __restrict__ C, int M,
                                                 const float* __restrict__ a_s,
                                                 const float* __restrict__ a_d,
                                                 float* __restrict__ hs,
                                                 float* __restrict__ hd) {
    __shared__ float As[2][16][128];
    __shared__ float Bs[2][16][128];
    const int tid = threadIdx.x;
    const int m0 = blockIdx.x * 128;
    const int n0 = blockIdx.y * 128;
    const int tx = tid & 15, ty = tid >> 4;

    u64t acc[8][4];
#pragma unroll
    for (int i = 0; i < 8; i++)
#pragma unroll
        for (int j = 0; j < 4; j++) acc[i][j] = 0ull;

    gemm_load_tile(A, W, M, m0, n0, 0, RELU, As[0], Bs[0], tid);
    __syncthreads();

    int buf = 0;
    for (int k0 = 0; k0 < 256; k0 += 16) {
        if (k0 < 240)
            gemm_load_tile(A, W, M, m0, n0, k0 + 16, RELU, As[buf ^ 1], Bs[buf ^ 1], tid);
#pragma unroll
        for (int kk = 0; kk < 16; kk++) {
            float4 av0 = *(const float4*)&As[buf][kk][ty * 8];
            float4 av1 = *(const float4*)&As[buf][kk][ty * 8 + 4];
            float4 bv0 = *(const float4*)&Bs[buf][kk][tx * 8];
            float4 bv1 = *(const float4*)&Bs[buf][kk][tx * 8 + 4];
            u64t bp[4];
            bp[0] = packf2(bv0.x, bv0.y);
            bp[1] = packf2(bv0.z, bv0.w);
            bp[2] = packf2(bv1.x, bv1.y);
            bp[3] = packf2(bv1.z, bv1.w);
            u64t ap[8];
            ap[0] = packf2(av0.x, av0.x);
            ap[1] = packf2(av0.y, av0.y);
            ap[2] = packf2(av0.z, av0.z);
            ap[3] = packf2(av0.w, av0.w);
            ap[4] = packf2(av1.x, av1.x);
            ap[5] = packf2(av1.y, av1.y);
            ap[6] = packf2(av1.z, av1.z);
            ap[7] = packf2(av1.w, av1.w);
#pragma unroll
            for (int i = 0; i < 8; i++)
#pragma unroll
                for (int j = 0; j < 4; j++) fma2(acc[i][j], ap[i], bp[j], acc[i][j]);
        }
        __syncthreads();
        buf ^= 1;
    }

    float as0[8], ad0[8];
    if (SCORES) {
#pragma unroll
        for (int j = 0; j < 8; j++) {
            as0[j] = __ldg(a_s + n0 + tx * 8 + j);
            ad0[j] = __ldg(a_d + n0 + tx * 8 + j);
        }
    }

#pragma unroll
    for (int i = 0; i < 8; i++) {
        int r = m0 + ty * 8 + i;
        float v[8];
        unpackf2(v[0], v[1], acc[i][0]);
        unpackf2(v[2], v[3], acc[i][1]);
        unpackf2(v[4], v[5], acc[i][2]);
        unpackf2(v[6], v[7], acc[i][3]);
        if (r < M) {
            *(float4*)(C + (size_t)r * FF + n0 + tx * 8)     = make_float4(v[0], v[1], v[2], v[3]);
            *(float4*)(C + (size_t)r * FF + n0 + tx * 8 + 4) = make_float4(v[4], v[5], v[6], v[7]);
        }
        if (SCORES) {
            float ps = 0.f, pd = 0.f;
#pragma unroll
            for (int j = 0; j < 8; j++) { ps += v[j] * as0[j]; pd += v[j] * ad0[j]; }
#pragma unroll
            for (int o = 8; o > 0; o >>= 1) {
                ps += __shfl_xor_sync(0xffffffffu, ps, o);
                pd += __shfl_xor_sync(0xffffffffu, pd, o);
            }
            if ((tid & 15) == 0 && r < M) {
                atomicAdd(hs + r, ps);
                atomicAdd(hd + r, pd);
            }
        }
    }
}

// ---------------- GCN gather: warp per node (combined graph) ----------------
__global__ void k_gcn_gather(const int* __restrict__ off, const int* __restrict__ csr,
                             const float* __restrict__ h, float* __restrict__ out,
                             const float* __restrict__ dinv,
                             const float* __restrict__ bab, const float* __restrict__ bag,
                             int n, int nsplit) {
    int w = (blockIdx.x * blockDim.x + threadIdx.x) >> 5;
    int lane = threadIdx.x & 31;
    if (w >= n) return;
    int e0 = off[w], e1 = off[w + 1];
    float dv = dinv[w];
    float4 a0 = make_float4(0.f, 0.f, 0.f, 0.f);
    float4 a1 = make_float4(0.f, 0.f, 0.f, 0.f);
    for (int base = e0; base < e1; base += 32) {
        int e = base + lane;
        int idx = (e < e1) ? csr[e] : 0;
        float wv = (e < e1) ? dinv[idx] : 0.f;
        int cnt = min(32, e1 - base);
        for (int k = 0; k < cnt; k++) {
            int s = __shfl_sync(0xffffffffu, idx, k);
            float ws = __shfl_sync(0xffffffffu, wv, k);
            const float4* hp = (const float4*)(h + (size_t)s * FF) + lane;
            float4 v0 = hp[0];
            float4 v1 = hp[32];
            a0.x += v0.x * ws; a0.y += v0.y * ws; a0.z += v0.z * ws; a0.w += v0.w * ws;
            a1.x += v1.x * ws; a1.y += v1.y * ws; a1.z += v1.z * ws; a1.w += v1.w * ws;
        }
    }
    {
        const float4* hp = (const float4*)(h + (size_t)w * FF) + lane;
        float4 v0 = hp[0], v1 = hp[32];
        a0.x += v0.x * dv; a0.y += v0.y * dv; a0.z += v0.z * dv; a0.w += v0.w * dv;
        a1.x += v1.x * dv; a1.y += v1.y * dv; a1.z += v1.z * dv; a1.w += v1.w * dv;
    }
    const float* b = (w < nsplit) ? bab : bag;
    float4 b0 = *((const float4*)b + lane);
    float4 b1 = *((const float4*)b + lane + 32);
    float4 o0 = make_float4(a0.x * dv + b0.x, a0.y * dv + b0.y, a0.z * dv + b0.z, a0.w * dv + b0.w);
    float4 o1 = make_float4(a1.x * dv + b1.x, a1.y * dv + b1.y, a1.z * dv + b1.z, a1.w * dv + b1.w);
    float4* op = (float4*)(out + (size_t)w * FF) + lane;
    op[0] = o0;
    op[32] = o1;
}

// ---------------- BN ----------------
__global__ void k_stats4(const float* __restrict__ p0, const float* __restrict__ p1,
                         const float* __restrict__ p2, const float* __restrict__ p3,
                         int nrows, float* __restrict__ sum, float* __restrict__ sq) {
    int seg = blockIdx.y;
    const float* X = (seg == 0) ? p0 : (seg == 1) ? p1 : (seg == 2) ? p2 : p3;
    int c = threadIdx.x;
    float s = 0.f, q = 0.f;
    for (int r = blockIdx.x; r < nrows; r += gridDim.x) {
        float v = X[(size_t)r * FF + c];
        s += v; q += v * v;
    }
    atomicAdd(&sum[seg * 256 + c], s);
    atomicAdd(&sq[seg * 256 + c], q);
}

__global__ void k_finalize(const float* __restrict__ sum, const float* __restrict__ sq,
                           float* __restrict__ mu, float* __restrict__ rstd, int n, int cnt) {
    int i = blockIdx.x * blockDim.x + threadIdx.x;
    if (i >= cnt) return;
    float m = sum[i] / n;
    mu[i] = m;
    rstd[i] = rsqrtf(sq[i] / n - m * m + EPS);
}

__global__ void k_bnrelu2(const float* __restrict__ X, float* __restrict__ Y,
                          const float* __restrict__ mu, const float* __restrict__ rstd,
                          const float* __restrict__ ga, const float* __restrict__ ba,
                          const float* __restrict__ gb, const float* __restrict__ bb,
                          int n, int nsplit) {
    size_t idx = (size_t)blockIdx.x * blockDim.x + threadIdx.x;
    if (idx >= (size_t)n * FF) return;
    int node = (int)(idx >> 8), c = (int)(idx & 255);
    bool lo = node < nsplit;
    int mc = lo ? c : c + 256;
    const float* g = lo ? ga : gb;
    const float* b = lo ? ba : bb;
    float v = (X[idx] - mu[mc]) * rstd[mc] * g[c] + b[c];
    Y[idx] = fmaxf(v, 0.f);
}

// ---------------- fused GAT per node ----------------
__global__ void k_gat_node(const int* __restrict__ off, const int* __restrict__ csr,
                           const float* __restrict__ h, float* __restrict__ out,
                           const float* __restrict__ hs, const float* __restrict__ hd,
                           const float* __restrict__ b, int n) {
    int w = (blockIdx.x * blockDim.x + threadIdx.x) >> 5;
    int lane = threadIdx.x & 31;
    if (w >= n) return;
    int e0 = off[w], e1 = off[w + 1];
    float hdn = hd[w];
    float self_e = lrelu(hs[w] + hdn);

    float m = (lane == 0) ? self_e : NINF;
    float s = (lane == 0) ? 1.f : 0.f;
    for (int e = e0 + lane; e < e1; e += 32) {
        float v = lrelu(hs[csr[e]] + hdn);
        if (v > m) { s = s * __expf(m - v) + 1.f; m = v; }
        else       { s += __expf(v - m); }
    }
#pragma unroll
    for (int o = 16; o > 0; o >>= 1) {
        float mo = __shfl_xor_sync(0xffffffffu, m, o);
        float so = __shfl_xor_sync(0xffffffffu, s, o);
        float mn = fmaxf(m, mo);
        s = s * __expf(m - mn) + so * __expf(mo - mn);
        m = mn;
    }
    float inv = 1.f / s;

    float4 a0, a1;
    {
        float sa = __expf(self_e - m) * inv;
        const float4* hp = (const float4*)(h + (size_t)w * FF) + lane;
        float4 v0 = hp[0], v1 = hp[32];
        a0 = make_float4(v0.x * sa, v0.y * sa, v0.z * sa, v0.w * sa);
        a1 = make_float4(v1.x * sa, v1.y * sa, v1.z * sa, v1.w * sa);
    }
    for (int base = e0; base < e1; base += 32) {
        int e = base + lane;
        int idx = (e < e1) ? csr[e] : 0;
        float al = 0.f;
        if (e < e1) al = __expf(lrelu(hs[idx] + hdn) - m) * inv;
        int cnt = min(32, e1 - base);
        for (int k = 0; k < cnt; k++) {
            int sn = __shfl_sync(0xffffffffu, idx, k);
            float av = __shfl_sync(0xffffffffu, al, k);
            const float4* hp = (const float4*)(h + (size_t)sn * FF) + lane;
            float4 v0 = hp[0];
            float4 v1 = hp[32];
            a0.x += v0.x * av; a0.y += v0.y * av; a0.z += v0.z * av; a0.w += v0.w * av;
            a1.x += v1.x * av; a1.y += v1.y * av; a1.z += v1.z * av; a1.w += v1.w * av;
        }
    }
    float4 b0 = *((const float4*)b + lane);
    float4 b1 = *((const float4*)b + lane + 32);
    a0.x += b0.x; a0.y += b0.y; a0.z += b0.z; a0.w += b0.w;
    a1.x += b1.x; a1.y += b1.y; a1.z += b1.z; a1.w += b1.w;
    float4* op = (float4*)(out + (size_t)w * FF) + lane;
    op[0] = a0;
    op[32] = a1;
}

// ---------------- final (merged both halves): relu(bn(concat[X,H])) @ Wfc + bfc ----------------
__global__ void k_final2(const float* __restrict__ Xp, const float* __restrict__ Hp,
                         const float* __restrict__ mu, const float* __restrict__ rstd,
                         const float* __restrict__ ga, const float* __restrict__ ba,
                         const float* __restrict__ Wa, const float* __restrict__ bfa,
                         const float* __restrict__ gb, const float* __restrict__ bb,
                         const float* __restrict__ Wb, const float* __restrict__ bfb,
                         float* __restrict__ out, int n, int nsplit) {
    int w = (blockIdx.x * blockDim.x + threadIdx.x) >> 5;
    int lane = threadIdx.x & 31;
    if (w >= n) return;
    bool lo = w < nsplit;
    int muoff = lo ? 0 : 512;
    const float* g   = lo ? ga  : gb;
    const float* b   = lo ? ba  : bb;
    const float* Wfc = lo ? Wa  : Wb;
    float bias = lo ? bfa[0] : bfb[0];
    float acc = 0.f;
#pragma unroll
    for (int j = 0; j < 16; j++) {
        int c = j * 32 + lane;
        float v = (c < FF) ? Xp[(size_t)w * FF + c] : Hp[(size_t)w * FF + (c - FF)];
        v = (v - mu[muoff + c]) * rstd[muoff + c] * g[c] + b[c];
        v = fmaxf(v, 0.f);
        acc += v * __ldg(Wfc + c);
    }
#pragma unroll
    for (int off = 16; off > 0; off >>= 1) acc += __shfl_down_sync(0xffffffffu, acc, off);
    if (lane == 0) out[w] = acc + bias;
}

// ---------------- host orchestration ----------------
static void gat_layer(const float* xin, bool relu_in, const float* W, const float* a_s,
                      const float* a_d, const float* b, float* hbuf, float* outbuf,
                      const int* off, const int* csr, float* sc) {
    k_fill<<<(2 * NTOT + 255) / 256, 256>>>(sc, 0.f, 2 * NTOT);
    dim3 gg((NTOT + 127) / 128, 2);
    if (relu_in) k_gemm256<true,  true><<<gg, 256>>>(xin, W, hbuf, NTOT, a_s, a_d, sc, sc + NTOT);
    else         k_gemm256<false, true><<<gg, 256>>>(xin, W, hbuf, NTOT, a_s, a_d, sc, sc + NTOT);
    k_gat_node<<<(NTOT * 32 + 255) / 256, 256>>>(off, csr, hbuf, outbuf, sc, sc + NTOT, b, NTOT);
}

extern "C" void kernel_launch(void* const* d_in, const int* in_sizes, int n_in,
                              void* d_out, int out_size) {
    const float* x_ab   = (const float*)d_in[0];
    const float* x_ag   = (const float*)d_in[1];
    const float* W_gcn  = (const float*)d_in[2];
    const float* b_gcn  = (const float*)d_in[3];
    const float* g1     = (const float*)d_in[4];
    const float* be1    = (const float*)d_in[5];
    const float* W_aggcn= (const float*)d_in[6];
    const float* b_aggcn= (const float*)d_in[7];
    const float* ag_g1  = (const float*)d_in[8];
    const float* ag_be1 = (const float*)d_in[9];
    const float* W_gat  = (const float*)d_in[10];
    const float* a_src  = (const float*)d_in[11];
    const float* a_dst  = (const float*)d_in[12];
    const float* b_gat  = (const float*)d_in[13];
    const float* W_gat2 = (const float*)d_in[14];
    const float* a_src2 = (const float*)d_in[15];
    const float* a_dst2 = (const float*)d_in[16];
    const float* b_gat2 = (const float*)d_in[17];
    const float* ag_g2  = (const float*)d_in[18];
    const float* ag_be2 = (const float*)d_in[19];
    const float* W_agfc = (const float*)d_in[20];
    const float* b_agfc = (const float*)d_in[21];
    const float* g2     = (const float*)d_in[22];
    const float* be2    = (const float*)d_in[23];
    const float* W_fc   = (const float*)d_in[24];
    const float* b_fc   = (const float*)d_in[25];
    const int* e_ab     = (const int*)d_in[26];
    const int* e_ag     = (const int*)d_in[27];
    const int* e_d      = (const int*)d_in[28];
    float* out = (float*)d_out;

    float *pX, *pA, *pB, *pdinv, *psc, *pss, *pmu, *prstd;
    int *pdegi, *pcur, *poff_g, *poff_d, *pcsr_g, *pcsr_d, *ppart;
    cudaGetSymbolAddress((void**)&pX, g_X);
    cudaGetSymbolAddress((void**)&pA, g_A);
    cudaGetSymbolAddress((void**)&pB, g_B);
    cudaGetSymbolAddress((void**)&pdinv, g_dinv);
    cudaGetSymbolAddress((void**)&psc, g_sc);
    cudaGetSymbolAddress((void**)&pss, g_sumsq);
    cudaGetSymbolAddress((void**)&pmu, g_mu);
    cudaGetSymbolAddress((void**)&prstd, g_rstd);
    cudaGetSymbolAddress((void**)&pdegi, g_degi);
    cudaGetSymbolAddress((void**)&pcur, g_cur);
    cudaGetSymbolAddress((void**)&poff_g, g_off_g);
    cudaGetSymbolAddress((void**)&poff_d, g_off_d);
    cudaGetSymbolAddress((void**)&pcsr_g, g_csr_g);
    cudaGetSymbolAddress((void**)&pcsr_d, g_csr_d);
    cudaGetSymbolAddress((void**)&ppart, g_partials);
    float* psum = pss;
    float* psq  = pss + 1024;

    const int* eab_src = e_ab;           const int* eab_dst = e_ab + EAB;
    const int* eag_src = e_ag;           const int* eag_dst = e_ag + EAG;
    const int* ed_src  = e_d;            const int* ed_dst  = e_d + ED;

    const int NB_TOT = (NTOT + SCAN_CHUNK - 1) / SCAN_CHUNK;   // 40

    // ---- launches 0-2: degree ----
    k_filli<<<(NTOT + 255) / 256, 256>>>(pdegi, 0, NTOT);                       // 0
    k_deg<<<(EAB + 255) / 256, 256>>>(eab_dst, EAB, pdegi);                     // 1
    k_deg<<<(EAG + 255) / 256, 256>>>(eag_dst, EAG, pdegi + NAB);               // 2
    // ---- launch 3: first GEMM (profiled by ncu) ----
    {
        dim3 gab((NAB + 127) / 128, 2);
        k_gemm256<false, false><<<gab, 256>>>(x_ab, W_gcn, pB, NAB,
                                              nullptr, nullptr, nullptr, nullptr);   // 3
        k_gemm256<false, false><<<gab, 256>>>(x_ag, W_aggcn, pB + (size_t)NAB * FF, NAB,
                                              nullptr, nullptr, nullptr, nullptr);   // 4
    }
    k_dinv<<<(NTOT + 255) / 256, 256>>>(pdegi, pdinv, NTOT);

    // ---- combined GCN CSR over NTOT ----
    k_scan1<<<NB_TOT, SCAN_T>>>(pdegi, NTOT, ppart);
    k_scan2<<<1, 64>>>(ppart, NB_TOT, poff_g, NTOT);
    k_scan3<<<NB_TOT, SCAN_T>>>(pdegi, NTOT, ppart, poff_g, pcur);
    k_scatter<<<(EAB + 255) / 256, 256>>>(eab_src, eab_dst, EAB, pcur, pcsr_g, 0, 0);
    k_scatter<<<(EAG + 255) / 256, 256>>>(eag_src, eag_dst, EAG, pcur, pcsr_g, NAB, NAB);

    // ---- GCN aggregate (gather) into g_A ----
    k_gcn_gather<<<(NTOT * 32 + 255) / 256, 256>>>(poff_g, pcsr_g, pB, pA, pdinv,
                                                   b_gcn, b_aggcn, NTOT, NAB);

    // ---- CSR build: d graph ----
    k_filli<<<(NTOT + 255) / 256, 256>>>(pdegi, 0, NTOT);
    k_deg<<<(ED + 255) / 256, 256>>>(ed_dst, ED, pdegi);
    k_scan1<<<NB_TOT, SCAN_T>>>(pdegi, NTOT, ppart);
    k_scan2<<<1, 64>>>(ppart, NB_TOT, poff_d, NTOT);
    k_scan3<<<NB_TOT, SCAN_T>>>(pdegi, NTOT, ppart, poff_d, pcur);
    k_scatter<<<(ED + 255) / 256, 256>>>(ed_src, ed_dst, ED, pcur, pcsr_d, 0, 0);

    // ---- BN1 + relu -> g_X ----
    k_fill<<<8, 256>>>(pss, 0.f, 2048);
    {
        dim3 gs(96, 2);
        k_stats4<<<gs, 256>>>(pA, pA + (size_t)NAB * FF, nullptr, nullptr, NAB, psum, psq);
    }
    k_finalize<<<2, 256>>>(psum, psq, pmu, prstd, NAB, 512);
    k_bnrelu2<<<((size_t)NTOT * FF + 255) / 256, 256>>>(pA, pX, pmu, prstd,
                                                        g1, be1, ag_g1, ag_be1, NTOT, NAB);

    // ---- GAT1: g_X -> g_A ; GAT2: relu(g_A) -> g_A ----
    gat_layer(pX, false, W_gat,  a_src,  a_dst,  b_gat,  pB, pA, poff_d, pcsr_d, psc);
    gat_layer(pA, true,  W_gat2, a_src2, a_dst2, b_gat2, pB, pA, poff_d, pcsr_d, psc);

    // ---- final BN stats over concat halves ----
    k_fill<<<8, 256>>>(pss, 0.f, 2048);
    {
        dim3 gs(96, 4);
        k_stats4<<<gs, 256>>>(pA, pX, pA + (size_t)NAB * FF, pX + (size_t)NAB * FF,
                              NAB, psum, psq);
    }
    k_finalize<<<4, 256>>>(psum, psq, pmu, prstd, NAB, 1024);

    // ---- final outputs (merged) ----
    k_final2<<<(NTOT * 32 + 255) / 256, 256>>>(pA, pX, pmu, prstd,
                                               g2, be2, W_fc, b_fc,
                                               ag_g2, ag_be2, W_agfc, b_agfc,
                                               out, NTOT, NAB);
}

// round 15
// speedup vs baseline: 1.7772x; 1.0375x over previous
#include <cuda_runtime.h>
#include <cstdint>

// ---------------- problem constants ----------------
constexpr int NAB  = 20000;
constexpr int NAG  = 20000;
constexpr int NTOT = NAB + NAG;      // 40000
constexpr int FF   = 256;
constexpr int EAB  = 320000;
constexpr int EAG  = 320000;
constexpr int ED   = 640000;
constexpr float EPS = 1e-5f;
constexpr float SLOPE = 0.2f;
constexpr float NINF = -3.0e38f;

// ---------------- scratch (device globals, no allocs) ----------------
__device__ float g_X[(size_t)NTOT * FF];
__device__ float g_A[(size_t)NTOT * FF];
__device__ float g_B[(size_t)NTOT * FF];
__device__ float g_dinv[NTOT];
__device__ float g_sc[2 * NTOT];            // hs | hd
__device__ float g_sumsq[2048];
__device__ float g_mu[1024], g_rstd[1024];

__device__ int g_degi[NTOT];
__device__ int g_cur[NTOT];
__device__ int g_off_g[NTOT + 1];
__device__ int g_off_d[NTOT + 1];
__device__ int g_csr_g[EAB + EAG];
__device__ int g_csr_d[ED];
__device__ int g_partials[64];

// ---------------- f32x2 helpers (sm_103a packed fp32 FMA) ----------------
typedef unsigned long long u64t;
__device__ __forceinline__ void fma2(u64t& d, u64t a, u64t b, u64t c) {
    asm("fma.rn.f32x2 %0, %1, %2, %3;" : "=l"(d) : "l"(a), "l"(b), "l"(c));
}
__device__ __forceinline__ u64t packf2(float lo, float hi) {
    u64t d;
    asm("mov.b64 %0, {%1, %2};" : "=l"(d) : "r"(__float_as_uint(lo)), "r"(__float_as_uint(hi)));
    return d;
}
__device__ __forceinline__ void unpackf2(float& lo, float& hi, u64t v) {
    unsigned int l, h;
    asm("mov.b64 {%0, %1}, %2;" : "=r"(l), "=r"(h) : "l"(v));
    lo = __uint_as_float(l); hi = __uint_as_float(h);
}

__device__ __forceinline__ float lrelu(float x) { return x > 0.f ? x : SLOPE * x; }

// ---------------- tiny utility kernels ----------------
__global__ void k_filli(int* p, int v, int n) {
    int i = blockIdx.x * blockDim.x + threadIdx.x;
    if (i < n) p[i] = v;
}
__global__ void k_fill(float* p, float v, int n) {
    int i = blockIdx.x * blockDim.x + threadIdx.x;
    if (i < n) p[i] = v;
}
__global__ void k_deg(const int* __restrict__ dst, int E, int* __restrict__ deg) {
    int i = blockIdx.x * blockDim.x + threadIdx.x;
    if (i < E) atomicAdd(&deg[dst[i]], 1);
}
__global__ void k_dinv(const int* __restrict__ deg, float* __restrict__ dinv, int n) {
    int i = blockIdx.x * blockDim.x + threadIdx.x;
    if (i < n) dinv[i] = rsqrtf((float)deg[i] + 1.0f);
}

// ---------------- parallel exclusive scan (3 kernels) ----------------
constexpr int SCAN_T = 256;
constexpr int SCAN_ITEMS = 4;
constexpr int SCAN_CHUNK = SCAN_T * SCAN_ITEMS;   // 1024

__global__ void k_scan1(const int* __restrict__ deg, int n, int* __restrict__ partials) {
    __shared__ int sh[SCAN_T];
    int b = blockIdx.x, t = threadIdx.x;
    int base = b * SCAN_CHUNK + t * SCAN_ITEMS;
    int s = 0;
#pragma unroll
    for (int k = 0; k < SCAN_ITEMS; k++) { int i = base + k; if (i < n) s += deg[i]; }
    sh[t] = s;
    __syncthreads();
    for (int d = 128; d > 0; d >>= 1) {
        if (t < d) sh[t] += sh[t + d];
        __syncthreads();
    }
    if (t == 0) partials[b] = sh[0];
}

__global__ void k_scan2(int* __restrict__ partials, int nb, int* __restrict__ off, int n) {
    __shared__ int sh[64];
    int t = threadIdx.x;
    int v = (t < nb) ? partials[t] : 0;
    sh[t] = v;
    __syncthreads();
    for (int d = 1; d < 64; d <<= 1) {
        int u = (t >= d) ? sh[t - d] : 0;
        __syncthreads();
        sh[t] += u;
        __syncthreads();
    }
    if (t < nb) partials[t] = sh[t] - v;
    if (t == 0) off[n] = sh[63];
}

// writes BOTH off[] and cur[]
__global__ void k_scan3(const int* __restrict__ deg, int n,
                        const int* __restrict__ partials, int* __restrict__ off,
                        int* __restrict__ cur) {
    __shared__ int sh[SCAN_T];
    int b = blockIdx.x, t = threadIdx.x;
    int base = b * SCAN_CHUNK + t * SCAN_ITEMS;
    int v[SCAN_ITEMS];
    int s = 0;
#pragma unroll
    for (int k = 0; k < SCAN_ITEMS; k++) { int i = base + k; v[k] = (i < n) ? deg[i] : 0; s += v[k]; }
    sh[t] = s;
    __syncthreads();
    for (int d = 1; d < SCAN_T; d <<= 1) {
        int u = (t >= d) ? sh[t - d] : 0;
        __syncthreads();
        sh[t] += u;
        __syncthreads();
    }
    int run = partials[b] + sh[t] - s;
#pragma unroll
    for (int k = 0; k < SCAN_ITEMS; k++) {
        int i = base + k;
        if (i < n) { off[i] = run; cur[i] = run; run += v[k]; }
    }
}

__global__ void k_scatter(const int* __restrict__ src, const int* __restrict__ dst, int E,
                          int* __restrict__ cur, int* __restrict__ csr,
                          int dstbase, int srcbase) {
    int i = blockIdx.x * blockDim.x + threadIdx.x;
    if (i >= E) return;
    int pos = atomicAdd(&cur[dst[i] + dstbase], 1);
    csr[pos] = src[i] + srcbase;
}

// ---------------- f32x2 SGEMM v3: reg-prefetch pipeline (no exposed LDG->STS stall) ----------------
struct TileRegs { float4 a0, a1, b0, b1; };

__device__ __forceinline__ void gemm_ldg(const float* __restrict__ A,
                                         const float* __restrict__ W, int M,
                                         int m0, int n0, int k0, int tid, TileRegs& t) {
    const int arow = tid >> 2;
    const int acol = (tid & 3) * 4;
    const int brow = tid >> 5;
    const int bcol = (tid & 31) * 4;
    int r0 = m0 + arow;          int rc0 = r0 < M ? r0 : M - 1;
    int r1 = m0 + arow + 64;     int rc1 = r1 < M ? r1 : M - 1;
    t.a0 = *(const float4*)(A + (size_t)rc0 * FF + k0 + acol);
    t.a1 = *(const float4*)(A + (size_t)rc1 * FF + k0 + acol);
    t.b0 = *(const float4*)(W + (size_t)(k0 + brow) * FF + n0 + bcol);
    t.b1 = *(const float4*)(W + (size_t)(k0 + brow + 8) * FF + n0 + bcol);
}

__device__ __forceinline__ void gemm_sts(const TileRegs& t,
                                         float (*As)[128], float (*Bs)[128], int tid) {
    const int arow = tid >> 2;
    const int acol = (tid & 3) * 4;
    const int brow = tid >> 5;
    const int bcol = (tid & 31) * 4;
    As[acol + 0][arow]      = t.a0.x;
    As[acol + 1][arow]      = t.a0.y;
    As[acol + 2][arow]      = t.a0.z;
    As[acol + 3][arow]      = t.a0.w;
    As[acol + 0][arow + 64] = t.a1.x;
    As[acol + 1][arow + 64] = t.a1.y;
    As[acol + 2][arow + 64] = t.a1.z;
    As[acol + 3][arow + 64] = t.a1.w;
    *(float4*)&Bs[brow][bcol]     = t.b0;
    *(float4*)&Bs[brow + 8][bcol] = t.b1;
}

template<bool SCORES>
__global__ void __launch_bounds__(256) k_gemm256(const float* __restrict__ A,
                                                 const float* __restrict__ W,
                                                 float* __restrict__ C, int M,
                                                 const float* __restrict__ a_s,
                                                 const float* __restrict__ a_d,
                                                 float* __restrict__ hs,
                                                 float* __restrict__ hd) {
    __shared__ float As[2][16][128];
    __shared__ float Bs[2][16][128];
    const int tid = threadIdx.x;
    const int m0 = blockIdx.x * 128;
    const int n0 = blockIdx.y * 128;
    const int tx = tid & 15, ty = tid >> 4;

    u64t acc[8][4];
#pragma unroll
    for (int i = 0; i < 8; i++)
#pragma unroll
        for (int j = 0; j < 4; j++) acc[i][j] = 0ull;

    TileRegs tr;
    gemm_ldg(A, W, M, m0, n0, 0, tid, tr);
    gemm_sts(tr, As[0], Bs[0], tid);
    __syncthreads();

    int buf = 0;
    for (int k0 = 0; k0 < 256; k0 += 16) {
        if (k0 < 240)
            gemm_ldg(A, W, M, m0, n0, k0 + 16, tid, tr);   // LDG issued; consumed after fma block
#pragma unroll
        for (int kk = 0; kk < 16; kk++) {
            float4 av0 = *(const float4*)&As[buf][kk][ty * 8];
            float4 av1 = *(const float4*)&As[buf][kk][ty * 8 + 4];
            float4 bv0 = *(const float4*)&Bs[buf][kk][tx * 8];
            float4 bv1 = *(const float4*)&Bs[buf][kk][tx * 8 + 4];
            u64t bp[4];
            bp[0] = packf2(bv0.x, bv0.y);
            bp[1] = packf2(bv0.z, bv0.w);
            bp[2] = packf2(bv1.x, bv1.y);
            bp[3] = packf2(bv1.z, bv1.w);
            u64t ap[8];
            ap[0] = packf2(av0.x, av0.x);
            ap[1] = packf2(av0.y, av0.y);
            ap[2] = packf2(av0.z, av0.z);
            ap[3] = packf2(av0.w, av0.w);
            ap[4] = packf2(av1.x, av1.x);
            ap[5] = packf2(av1.y, av1.y);
            ap[6] = packf2(av1.z, av1.z);
            ap[7] = packf2(av1.w, av1.w);
#pragma unroll
            for (int i = 0; i < 8; i++)
#pragma unroll
                for (int j = 0; j < 4; j++) fma2(acc[i][j], ap[i], bp[j], acc[i][j]);
        }
        if (k0 < 240)
            gemm_sts(tr, As[buf ^ 1], Bs[buf ^ 1], tid);   // LDG long drained by now
        __syncthreads();
        buf ^= 1;
    }

    float as0[8], ad0[8];
    if (SCORES) {
#pragma unroll
        for (int j = 0; j < 8; j++) {
            as0[j] = __ldg(a_s + n0 + tx * 8 + j);
            ad0[j] = __ldg(a_d + n0 + tx * 8 + j);
        }
    }

#pragma unroll
    for (int i = 0; i < 8; i++) {
        int r = m0 + ty * 8 + i;
        float v[8];
        unpackf2(v[0], v[1], acc[i][0]);
        unpackf2(v[2], v[3], acc[i][1]);
        unpackf2(v[4], v[5], acc[i][2]);
        unpackf2(v[6], v[7], acc[i][3]);
        if (r < M) {
            *(float4*)(C + (size_t)r * FF + n0 + tx * 8)     = make_float4(v[0], v[1], v[2], v[3]);
            *(float4*)(C + (size_t)r * FF + n0 + tx * 8 + 4) = make_float4(v[4], v[5], v[6], v[7]);
        }
        if (SCORES) {
            float ps = 0.f, pd = 0.f;
#pragma unroll
            for (int j = 0; j < 8; j++) { ps += v[j] * as0[j]; pd += v[j] * ad0[j]; }
#pragma unroll
            for (int o = 8; o > 0; o >>= 1) {
                ps += __shfl_xor_sync(0xffffffffu, ps, o);
                pd += __shfl_xor_sync(0xffffffffu, pd, o);
            }
            if ((tid & 15) == 0 && r < M) {
                atomicAdd(hs + r, ps);
                atomicAdd(hd + r, pd);
            }
        }
    }
}

// ---------------- GCN gather: warp per node (combined graph) ----------------
__global__ void k_gcn_gather(const int* __restrict__ off, const int* __restrict__ csr,
                             const float* __restrict__ h, float* __restrict__ out,
                             const float* __restrict__ dinv,
                             const float* __restrict__ bab, const float* __restrict__ bag,
                             int n, int nsplit) {
    int w = (blockIdx.x * blockDim.x + threadIdx.x) >> 5;
    int lane = threadIdx.x & 31;
    if (w >= n) return;
    int e0 = off[w], e1 = off[w + 1];
    float dv = dinv[w];
    float4 a0 = make_float4(0.f, 0.f, 0.f, 0.f);
    float4 a1 = make_float4(0.f, 0.f, 0.f, 0.f);
    for (int base = e0; base < e1; base += 32) {
        int e = base + lane;
        int idx = (e < e1) ? csr[e] : 0;
        float wv = (e < e1) ? dinv[idx] : 0.f;
        int cnt = min(32, e1 - base);
        for (int k = 0; k < cnt; k++) {
            int s = __shfl_sync(0xffffffffu, idx, k);
            float ws = __shfl_sync(0xffffffffu, wv, k);
            const float4* hp = (const float4*)(h + (size_t)s * FF) + lane;
            float4 v0 = hp[0];
            float4 v1 = hp[32];
            a0.x += v0.x * ws; a0.y += v0.y * ws; a0.z += v0.z * ws; a0.w += v0.w * ws;
            a1.x += v1.x * ws; a1.y += v1.y * ws; a1.z += v1.z * ws; a1.w += v1.w * ws;
        }
    }
    {
        const float4* hp = (const float4*)(h + (size_t)w * FF) + lane;
        float4 v0 = hp[0], v1 = hp[32];
        a0.x += v0.x * dv; a0.y += v0.y * dv; a0.z += v0.z * dv; a0.w += v0.w * dv;
        a1.x += v1.x * dv; a1.y += v1.y * dv; a1.z += v1.z * dv; a1.w += v1.w * dv;
    }
    const float* b = (w < nsplit) ? bab : bag;
    float4 b0 = *((const float4*)b + lane);
    float4 b1 = *((const float4*)b + lane + 32);
    float4 o0 = make_float4(a0.x * dv + b0.x, a0.y * dv + b0.y, a0.z * dv + b0.z, a0.w * dv + b0.w);
    float4 o1 = make_float4(a1.x * dv + b1.x, a1.y * dv + b1.y, a1.z * dv + b1.z, a1.w * dv + b1.w);
    float4* op = (float4*)(out + (size_t)w * FF) + lane;
    op[0] = o0;
    op[32] = o1;
}

// ---------------- BN ----------------
__global__ void k_stats4(const float* __restrict__ p0, const float* __restrict__ p1,
                         const float* __restrict__ p2, const float* __restrict__ p3,
                         int nrows, float* __restrict__ sum, float* __restrict__ sq) {
    int seg = blockIdx.y;
    const float* X = (seg == 0) ? p0 : (seg == 1) ? p1 : (seg == 2) ? p2 : p3;
    int c = threadIdx.x;
    float s = 0.f, q = 0.f;
    for (int r = blockIdx.x; r < nrows; r += gridDim.x) {
        float v = X[(size_t)r * FF + c];
        s += v; q += v * v;
    }
    atomicAdd(&sum[seg * 256 + c], s);
    atomicAdd(&sq[seg * 256 + c], q);
}

__global__ void k_finalize(const float* __restrict__ sum, const float* __restrict__ sq,
                           float* __restrict__ mu, float* __restrict__ rstd, int n, int cnt) {
    int i = blockIdx.x * blockDim.x + threadIdx.x;
    if (i >= cnt) return;
    float m = sum[i] / n;
    mu[i] = m;
    rstd[i] = rsqrtf(sq[i] / n - m * m + EPS);
}

__global__ void k_bnrelu2(const float* __restrict__ X, float* __restrict__ Y,
                          const float* __restrict__ mu, const float* __restrict__ rstd,
                          const float* __restrict__ ga, const float* __restrict__ ba,
                          const float* __restrict__ gb, const float* __restrict__ bb,
                          int n, int nsplit) {
    size_t idx = (size_t)blockIdx.x * blockDim.x + threadIdx.x;
    if (idx >= (size_t)n * FF) return;
    int node = (int)(idx >> 8), c = (int)(idx & 255);
    bool lo = node < nsplit;
    int mc = lo ? c : c + 256;
    const float* g = lo ? ga : gb;
    const float* b = lo ? ba : bb;
    float v = (X[idx] - mu[mc]) * rstd[mc] * g[c] + b[c];
    Y[idx] = fmaxf(v, 0.f);
}

// ---------------- fused GAT per node (optional output relu) ----------------
__global__ void k_gat_node(const int* __restrict__ off, const int* __restrict__ csr,
                           const float* __restrict__ h, float* __restrict__ out,
                           const float* __restrict__ hs, const float* __restrict__ hd,
                           const float* __restrict__ b, int n, int relu_out) {
    int w = (blockIdx.x * blockDim.x + threadIdx.x) >> 5;
    int lane = threadIdx.x & 31;
    if (w >= n) return;
    int e0 = off[w], e1 = off[w + 1];
    float hdn = hd[w];
    float self_e = lrelu(hs[w] + hdn);

    float m = (lane == 0) ? self_e : NINF;
    float s = (lane == 0) ? 1.f : 0.f;
    for (int e = e0 + lane; e < e1; e += 32) {
        float v = lrelu(hs[csr[e]] + hdn);
        if (v > m) { s = s * __expf(m - v) + 1.f; m = v; }
        else       { s += __expf(v - m); }
    }
#pragma unroll
    for (int o = 16; o > 0; o >>= 1) {
        float mo = __shfl_xor_sync(0xffffffffu, m, o);
        float so = __shfl_xor_sync(0xffffffffu, s, o);
        float mn = fmaxf(m, mo);
        s = s * __expf(m - mn) + so * __expf(mo - mn);
        m = mn;
    }
    float inv = 1.f / s;

    float4 a0, a1;
    {
        float sa = __expf(self_e - m) * inv;
        const float4* hp = (const float4*)(h + (size_t)w * FF) + lane;
        float4 v0 = hp[0], v1 = hp[32];
        a0 = make_float4(v0.x * sa, v0.y * sa, v0.z * sa, v0.w * sa);
        a1 = make_float4(v1.x * sa, v1.y * sa, v1.z * sa, v1.w * sa);
    }
    for (int base = e0; base < e1; base += 32) {
        int e = base + lane;
        int idx = (e < e1) ? csr[e] : 0;
        float al = 0.f;
        if (e < e1) al = __expf(lrelu(hs[idx] + hdn) - m) * inv;
        int cnt = min(32, e1 - base);
        for (int k = 0; k < cnt; k++) {
            int sn = __shfl_sync(0xffffffffu, idx, k);
            float av = __shfl_sync(0xffffffffu, al, k);
            const float4* hp = (const float4*)(h + (size_t)sn * FF) + lane;
            float4 v0 = hp[0];
            float4 v1 = hp[32];
            a0.x += v0.x * av; a0.y += v0.y * av; a0.z += v0.z * av; a0.w += v0.w * av;
            a1.x += v1.x * av; a1.y += v1.y * av; a1.z += v1.z * av; a1.w += v1.w * av;
        }
    }
    float4 b0 = *((const float4*)b + lane);
    float4 b1 = *((const float4*)b + lane + 32);
    a0.x += b0.x; a0.y += b0.y; a0.z += b0.z; a0.w += b0.w;
    a1.x += b1.x; a1.y += b1.y; a1.z += b1.z; a1.w += b1.w;
    if (relu_out) {
        a0.x = fmaxf(a0.x, 0.f); a0.y = fmaxf(a0.y, 0.f);
        a0.z = fmaxf(a0.z, 0.f); a0.w = fmaxf(a0.w, 0.f);
        a1.x = fmaxf(a1.x, 0.f); a1.y = fmaxf(a1.y, 0.f);
        a1.z = fmaxf(a1.z, 0.f); a1.w = fmaxf(a1.w, 0.f);
    }
    float4* op = (float4*)(out + (size_t)w * FF) + lane;
    op[0] = a0;
    op[32] = a1;
}

// ---------------- final (merged both halves): relu(bn(concat[X,H])) @ Wfc + bfc ----------------
__global__ void k_final2(const float* __restrict__ Xp, const float* __restrict__ Hp,
                         const float* __restrict__ mu, const float* __restrict__ rstd,
                         const float* __restrict__ ga, const float* __restrict__ ba,
                         const float* __restrict__ Wa, const float* __restrict__ bfa,
                         const float* __restrict__ gb, const float* __restrict__ bb,
                         const float* __restrict__ Wb, const float* __restrict__ bfb,
                         float* __restrict__ out, int n, int nsplit) {
    int w = (blockIdx.x * blockDim.x + threadIdx.x) >> 5;
    int lane = threadIdx.x & 31;
    if (w >= n) return;
    bool lo = w < nsplit;
    int muoff = lo ? 0 : 512;
    const float* g   = lo ? ga  : gb;
    const float* b   = lo ? ba  : bb;
    const float* Wfc = lo ? Wa  : Wb;
    float bias = lo ? bfa[0] : bfb[0];
    float acc = 0.f;
#pragma unroll
    for (int j = 0; j < 16; j++) {
        int c = j * 32 + lane;
        float v = (c < FF) ? Xp[(size_t)w * FF + c] : Hp[(size_t)w * FF + (c - FF)];
        v = (v - mu[muoff + c]) * rstd[muoff + c] * g[c] + b[c];
        v = fmaxf(v, 0.f);
        acc += v * __ldg(Wfc + c);
    }
#pragma unroll
    for (int off = 16; off > 0; off >>= 1) acc += __shfl_down_sync(0xffffffffu, acc, off);
    if (lane == 0) out[w] = acc + bias;
}

// ---------------- host orchestration ----------------
static void gat_layer(const float* xin, const float* W, const float* a_s,
                      const float* a_d, const float* b, float* hbuf, float* outbuf,
                      const int* off, const int* csr, float* sc, int relu_out) {
    k_fill<<<(2 * NTOT + 255) / 256, 256>>>(sc, 0.f, 2 * NTOT);
    dim3 gg((NTOT + 127) / 128, 2);
    k_gemm256<true><<<gg, 256>>>(xin, W, hbuf, NTOT, a_s, a_d, sc, sc + NTOT);
    k_gat_node<<<(NTOT * 32 + 255) / 256, 256>>>(off, csr, hbuf, outbuf, sc, sc + NTOT,
                                                 b, NTOT, relu_out);
}

extern "C" void kernel_launch(void* const* d_in, const int* in_sizes, int n_in,
                              void* d_out, int out_size) {
    const float* x_ab   = (const float*)d_in[0];
    const float* x_ag   = (const float*)d_in[1];
    const float* W_gcn  = (const float*)d_in[2];
    const float* b_gcn  = (const float*)d_in[3];
    const float* g1     = (const float*)d_in[4];
    const float* be1    = (const float*)d_in[5];
    const float* W_aggcn= (const float*)d_in[6];
    const float* b_aggcn= (const float*)d_in[7];
    const float* ag_g1  = (const float*)d_in[8];
    const float* ag_be1 = (const float*)d_in[9];
    const float* W_gat  = (const float*)d_in[10];
    const float* a_src  = (const float*)d_in[11];
    const float* a_dst  = (const float*)d_in[12];
    const float* b_gat  = (const float*)d_in[13];
    const float* W_gat2 = (const float*)d_in[14];
    const float* a_src2 = (const float*)d_in[15];
    const float* a_dst2 = (const float*)d_in[16];
    const float* b_gat2 = (const float*)d_in[17];
    const float* ag_g2  = (const float*)d_in[18];
    const float* ag_be2 = (const float*)d_in[19];
    const float* W_agfc = (const float*)d_in[20];
    const float* b_agfc = (const float*)d_in[21];
    const float* g2     = (const float*)d_in[22];
    const float* be2    = (const float*)d_in[23];
    const float* W_fc   = (const float*)d_in[24];
    const float* b_fc   = (const float*)d_in[25];
    const int* e_ab     = (const int*)d_in[26];
    const int* e_ag     = (const int*)d_in[27];
    const int* e_d      = (const int*)d_in[28];
    float* out = (float*)d_out;

    float *pX, *pA, *pB, *pdinv, *psc, *pss, *pmu, *prstd;
    int *pdegi, *pcur, *poff_g, *poff_d, *pcsr_g, *pcsr_d, *ppart;
    cudaGetSymbolAddress((void**)&pX, g_X);
    cudaGetSymbolAddress((void**)&pA, g_A);
    cudaGetSymbolAddress((void**)&pB, g_B);
    cudaGetSymbolAddress((void**)&pdinv, g_dinv);
    cudaGetSymbolAddress((void**)&psc, g_sc);
    cudaGetSymbolAddress((void**)&pss, g_sumsq);
    cudaGetSymbolAddress((void**)&pmu, g_mu);
    cudaGetSymbolAddress((void**)&prstd, g_rstd);
    cudaGetSymbolAddress((void**)&pdegi, g_degi);
    cudaGetSymbolAddress((void**)&pcur, g_cur);
    cudaGetSymbolAddress((void**)&poff_g, g_off_g);
    cudaGetSymbolAddress((void**)&poff_d, g_off_d);
    cudaGetSymbolAddress((void**)&pcsr_g, g_csr_g);
    cudaGetSymbolAddress((void**)&pcsr_d, g_csr_d);
    cudaGetSymbolAddress((void**)&ppart, g_partials);
    float* psum = pss;
    float* psq  = pss + 1024;

    const int* eab_src = e_ab;           const int* eab_dst = e_ab + EAB;
    const int* eag_src = e_ag;           const int* eag_dst = e_ag + EAG;
    const int* ed_src  = e_d;            const int* ed_dst  = e_d + ED;

    const int NB_TOT = (NTOT + SCAN_CHUNK - 1) / SCAN_CHUNK;   // 40

    // ---- launches 0-2: degree ----
    k_filli<<<(NTOT + 255) / 256, 256>>>(pdegi, 0, NTOT);                       // 0
    k_deg<<<(EAB + 255) / 256, 256>>>(eab_dst, EAB, pdegi);                     // 1
    k_deg<<<(EAG + 255) / 256, 256>>>(eag_dst, EAG, pdegi + NAB);               // 2
    // ---- launch 3: first GEMM (profiled by ncu) ----
    {
        dim3 gab((NAB + 127) / 128, 2);
        k_gemm256<false><<<gab, 256>>>(x_ab, W_gcn, pB, NAB,
                                       nullptr, nullptr, nullptr, nullptr);     // 3
        k_gemm256<false><<<gab, 256>>>(x_ag, W_aggcn, pB + (size_t)NAB * FF, NAB,
                                       nullptr, nullptr, nullptr, nullptr);     // 4
    }
    k_dinv<<<(NTOT + 255) / 256, 256>>>(pdegi, pdinv, NTOT);

    // ---- combined GCN CSR over NTOT ----
    k_scan1<<<NB_TOT, SCAN_T>>>(pdegi, NTOT, ppart);
    k_scan2<<<1, 64>>>(ppart, NB_TOT, poff_g, NTOT);
    k_scan3<<<NB_TOT, SCAN_T>>>(pdegi, NTOT, ppart, poff_g, pcur);
    k_scatter<<<(EAB + 255) / 256, 256>>>(eab_src, eab_dst, EAB, pcur, pcsr_g, 0, 0);
    k_scatter<<<(EAG + 255) / 256, 256>>>(eag_src, eag_dst, EAG, pcur, pcsr_g, NAB, NAB);

    // ---- GCN aggregate (gather) into g_A ----
    k_gcn_gather<<<(NTOT * 32 + 255) / 256, 256>>>(poff_g, pcsr_g, pB, pA, pdinv,
                                                   b_gcn, b_aggcn, NTOT, NAB);

    // ---- CSR build: d graph ----
    k_filli<<<(NTOT + 255) / 256, 256>>>(pdegi, 0, NTOT);
    k_deg<<<(ED + 255) / 256, 256>>>(ed_dst, ED, pdegi);
    k_scan1<<<NB_TOT, SCAN_T>>>(pdegi, NTOT, ppart);
    k_scan2<<<1, 64>>>(ppart, NB_TOT, poff_d, NTOT);
    k_scan3<<<NB_TOT, SCAN_T>>>(pdegi, NTOT, ppart, poff_d, pcur);
    k_scatter<<<(ED + 255) / 256, 256>>>(ed_src, ed_dst, ED, pcur, pcsr_d, 0, 0);

    // ---- BN1 + relu -> g_X ----
    k_fill<<<8, 256>>>(pss, 0.f, 2048);
    {
        dim3 gs(96, 2);
        k_stats4<<<gs, 256>>>(pA, pA + (size_t)NAB * FF, nullptr, nullptr, NAB, psum, psq);
    }
    k_finalize<<<2, 256>>>(psum, psq, pmu, prstd, NAB, 512);
    k_bnrelu2<<<((size_t)NTOT * FF + 255) / 256, 256>>>(pA, pX, pmu, prstd,
                                                        g1, be1, ag_g1, ag_be1, NTOT, NAB);

    // ---- GAT1 (relu fused into gat_node output) ; GAT2 ----
    gat_layer(pX, W_gat,  a_src,  a_dst,  b_gat,  pB, pA, poff_d, pcsr_d, psc, 1);
    gat_layer(pA, W_gat2, a_src2, a_dst2, b_gat2, pB, pA, poff_d, pcsr_d, psc, 0);

    // ---- final BN stats over concat halves ----
    k_fill<<<8, 256>>>(pss, 0.f, 2048);
    {
        dim3 gs(96, 4);
        k_stats4<<<gs, 256>>>(pA, pX, pA + (size_t)NAB * FF, pX + (size_t)NAB * FF,
                              NAB, psum, psq);
    }
    k_finalize<<<4, 256>>>(psum, psq, pmu, prstd, NAB, 1024);

    // ---- final outputs (merged) ----
    k_final2<<<(NTOT * 32 + 255) / 256, 256>>>(pA, pX, pmu, prstd,
                                               g2, be2, W_fc, b_fc,
                                               ag_g2, ag_be2, W_agfc, b_agfc,
                                               out, NTOT, NAB);
}

// round 16
// speedup vs baseline: 1.8380x; 1.0342x over previous
#include <cuda_runtime.h>
#include <cstdint>

// ---------------- problem constants ----------------
constexpr int NAB  = 20000;
constexpr int NAG  = 20000;
constexpr int NTOT = NAB + NAG;      // 40000
constexpr int FF   = 256;
constexpr int EAB  = 320000;
constexpr int EAG  = 320000;
constexpr int ED   = 640000;
constexpr float EPS = 1e-5f;
constexpr float SLOPE = 0.2f;
constexpr float NINF = -3.0e38f;

// ---------------- scratch (device globals, no allocs) ----------------
__device__ float g_X[(size_t)NTOT * FF];
__device__ float g_A[(size_t)NTOT * FF];
__device__ float g_B[(size_t)NTOT * FF];
__device__ float g_dinv[NTOT];
__device__ float g_sc[2 * NTOT];            // hs | hd
__device__ float g_sumsq[2048];
__device__ float g_mu[1024], g_rstd[1024];

__device__ int g_degi[NTOT];
__device__ int g_cur[NTOT];
__device__ int g_off_g[NTOT + 1];
__device__ int g_off_d[NTOT + 1];
__device__ int g_csr_g[EAB + EAG];
__device__ int g_csr_d[ED];
__device__ int g_partials[64];

// ---------------- f32x2 helpers (sm_103a packed fp32 FMA) ----------------
typedef unsigned long long u64t;
__device__ __forceinline__ void fma2(u64t& d, u64t a, u64t b, u64t c) {
    asm("fma.rn.f32x2 %0, %1, %2, %3;" : "=l"(d) : "l"(a), "l"(b), "l"(c));
}
__device__ __forceinline__ u64t packf2(float lo, float hi) {
    u64t d;
    asm("mov.b64 %0, {%1, %2};" : "=l"(d) : "r"(__float_as_uint(lo)), "r"(__float_as_uint(hi)));
    return d;
}
__device__ __forceinline__ void unpackf2(float& lo, float& hi, u64t v) {
    unsigned int l, h;
    asm("mov.b64 {%0, %1}, %2;" : "=r"(l), "=r"(h) : "l"(v));
    lo = __uint_as_float(l); hi = __uint_as_float(h);
}

__device__ __forceinline__ float lrelu(float x) { return x > 0.f ? x : SLOPE * x; }

// ---------------- tiny utility kernels ----------------
__global__ void k_filli(int* p, int v, int n) {
    int i = blockIdx.x * blockDim.x + threadIdx.x;
    if (i < n) p[i] = v;
}
__global__ void k_fill(float* p, float v, int n) {
    int i = blockIdx.x * blockDim.x + threadIdx.x;
    if (i < n) p[i] = v;
}
// two edge lists in one pass
__global__ void k_deg2(const int* __restrict__ d0, int E0,
                       const int* __restrict__ d1, int E1,
                       int* __restrict__ deg, int base1) {
    int i = blockIdx.x * blockDim.x + threadIdx.x;
    if (i < E0) atomicAdd(&deg[d0[i]], 1);
    else if (i < E0 + E1) atomicAdd(&deg[d1[i - E0] + base1], 1);
}
__global__ void k_deg(const int* __restrict__ dst, int E, int* __restrict__ deg) {
    int i = blockIdx.x * blockDim.x + threadIdx.x;
    if (i < E) atomicAdd(&deg[dst[i]], 1);
}
__global__ void k_dinv(const int* __restrict__ deg, float* __restrict__ dinv, int n) {
    int i = blockIdx.x * blockDim.x + threadIdx.x;
    if (i < n) dinv[i] = rsqrtf((float)deg[i] + 1.0f);
}

// ---------------- parallel exclusive scan (3 kernels) ----------------
constexpr int SCAN_T = 256;
constexpr int SCAN_ITEMS = 4;
constexpr int SCAN_CHUNK = SCAN_T * SCAN_ITEMS;   // 1024

__global__ void k_scan1(const int* __restrict__ deg, int n, int* __restrict__ partials) {
    __shared__ int sh[SCAN_T];
    int b = blockIdx.x, t = threadIdx.x;
    int base = b * SCAN_CHUNK + t * SCAN_ITEMS;
    int s = 0;
#pragma unroll
    for (int k = 0; k < SCAN_ITEMS; k++) { int i = base + k; if (i < n) s += deg[i]; }
    sh[t] = s;
    __syncthreads();
    for (int d = 128; d > 0; d >>= 1) {
        if (t < d) sh[t] += sh[t + d];
        __syncthreads();
    }
    if (t == 0) partials[b] = sh[0];
}

__global__ void k_scan2(int* __restrict__ partials, int nb, int* __restrict__ off, int n) {
    __shared__ int sh[64];
    int t = threadIdx.x;
    int v = (t < nb) ? partials[t] : 0;
    sh[t] = v;
    __syncthreads();
    for (int d = 1; d < 64; d <<= 1) {
        int u = (t >= d) ? sh[t - d] : 0;
        __syncthreads();
        sh[t] += u;
        __syncthreads();
    }
    if (t < nb) partials[t] = sh[t] - v;
    if (t == 0) off[n] = sh[63];
}

// writes BOTH off[] and cur[]
__global__ void k_scan3(const int* __restrict__ deg, int n,
                        const int* __restrict__ partials, int* __restrict__ off,
                        int* __restrict__ cur) {
    __shared__ int sh[SCAN_T];
    int b = blockIdx.x, t = threadIdx.x;
    int base = b * SCAN_CHUNK + t * SCAN_ITEMS;
    int v[SCAN_ITEMS];
    int s = 0;
#pragma unroll
    for (int k = 0; k < SCAN_ITEMS; k++) { int i = base + k; v[k] = (i < n) ? deg[i] : 0; s += v[k]; }
    sh[t] = s;
    __syncthreads();
    for (int d = 1; d < SCAN_T; d <<= 1) {
        int u = (t >= d) ? sh[t - d] : 0;
        __syncthreads();
        sh[t] += u;
        __syncthreads();
    }
    int run = partials[b] + sh[t] - s;
#pragma unroll
    for (int k = 0; k < SCAN_ITEMS; k++) {
        int i = base + k;
        if (i < n) { off[i] = run; cur[i] = run; run += v[k]; }
    }
}

__global__ void k_scatter(const int* __restrict__ src, const int* __restrict__ dst, int E,
                          int* __restrict__ cur, int* __restrict__ csr,
                          int dstbase, int srcbase) {
    int i = blockIdx.x * blockDim.x + threadIdx.x;
    if (i >= E) return;
    int pos = atomicAdd(&cur[dst[i] + dstbase], 1);
    csr[pos] = src[i] + srcbase;
}
// two edge lists in one pass (second list node ids offset by base1)
__global__ void k_scatter2(const int* __restrict__ s0, const int* __restrict__ d0, int E0,
                           const int* __restrict__ s1, const int* __restrict__ d1, int E1,
                           int* __restrict__ cur, int* __restrict__ csr, int base1) {
    int i = blockIdx.x * blockDim.x + threadIdx.x;
    if (i < E0) {
        int pos = atomicAdd(&cur[d0[i]], 1);
        csr[pos] = s0[i];
    } else if (i < E0 + E1) {
        int j = i - E0;
        int pos = atomicAdd(&cur[d1[j] + base1], 1);
        csr[pos] = s1[j] + base1;
    }
}

// ---------------- f32x2 SGEMM v3: reg-prefetch pipeline ----------------
struct TileRegs { float4 a0, a1, b0, b1; };

__device__ __forceinline__ void gemm_ldg(const float* __restrict__ A,
                                         const float* __restrict__ W, int M,
                                         int m0, int n0, int k0, int tid, TileRegs& t) {
    const int arow = tid >> 2;
    const int acol = (tid & 3) * 4;
    const int brow = tid >> 5;
    const int bcol = (tid & 31) * 4;
    int r0 = m0 + arow;          int rc0 = r0 < M ? r0 : M - 1;
    int r1 = m0 + arow + 64;     int rc1 = r1 < M ? r1 : M - 1;
    t.a0 = *(const float4*)(A + (size_t)rc0 * FF + k0 + acol);
    t.a1 = *(const float4*)(A + (size_t)rc1 * FF + k0 + acol);
    t.b0 = *(const float4*)(W + (size_t)(k0 + brow) * FF + n0 + bcol);
    t.b1 = *(const float4*)(W + (size_t)(k0 + brow + 8) * FF + n0 + bcol);
}

__device__ __forceinline__ void gemm_sts(const TileRegs& t,
                                         float (*As)[128], float (*Bs)[128], int tid) {
    const int arow = tid >> 2;
    const int acol = (tid & 3) * 4;
    const int brow = tid >> 5;
    const int bcol = (tid & 31) * 4;
    As[acol + 0][arow]      = t.a0.x;
    As[acol + 1][arow]      = t.a0.y;
    As[acol + 2][arow]      = t.a0.z;
    As[acol + 3][arow]      = t.a0.w;
    As[acol + 0][arow + 64] = t.a1.x;
    As[acol + 1][arow + 64] = t.a1.y;
    As[acol + 2][arow + 64] = t.a1.z;
    As[acol + 3][arow + 64] = t.a1.w;
    *(float4*)&Bs[brow][bcol]     = t.b0;
    *(float4*)&Bs[brow + 8][bcol] = t.b1;
}

// core mainloop + epilogue shared by both GEMM entry points
template<bool SCORES>
__device__ __forceinline__ void gemm_body(const float* __restrict__ A,
                                          const float* __restrict__ W,
                                          float* __restrict__ C, int M,
                                          int m0, int n0,
                                          const float* __restrict__ a_s,
                                          const float* __restrict__ a_d,
                                          float* __restrict__ hs,
                                          float* __restrict__ hd,
                                          float (*As)[16][128], float (*Bs)[16][128]) {
    const int tid = threadIdx.x;
    const int tx = tid & 15, ty = tid >> 4;

    u64t acc[8][4];
#pragma unroll
    for (int i = 0; i < 8; i++)
#pragma unroll
        for (int j = 0; j < 4; j++) acc[i][j] = 0ull;

    TileRegs tr;
    gemm_ldg(A, W, M, m0, n0, 0, tid, tr);
    gemm_sts(tr, As[0], Bs[0], tid);
    __syncthreads();

    int buf = 0;
    for (int k0 = 0; k0 < 256; k0 += 16) {
        if (k0 < 240)
            gemm_ldg(A, W, M, m0, n0, k0 + 16, tid, tr);
#pragma unroll
        for (int kk = 0; kk < 16; kk++) {
            float4 av0 = *(const float4*)&As[buf][kk][ty * 8];
            float4 av1 = *(const float4*)&As[buf][kk][ty * 8 + 4];
            float4 bv0 = *(const float4*)&Bs[buf][kk][tx * 8];
            float4 bv1 = *(const float4*)&Bs[buf][kk][tx * 8 + 4];
            u64t bp[4];
            bp[0] = packf2(bv0.x, bv0.y);
            bp[1] = packf2(bv0.z, bv0.w);
            bp[2] = packf2(bv1.x, bv1.y);
            bp[3] = packf2(bv1.z, bv1.w);
            u64t ap[8];
            ap[0] = packf2(av0.x, av0.x);
            ap[1] = packf2(av0.y, av0.y);
            ap[2] = packf2(av0.z, av0.z);
            ap[3] = packf2(av0.w, av0.w);
            ap[4] = packf2(av1.x, av1.x);
            ap[5] = packf2(av1.y, av1.y);
            ap[6] = packf2(av1.z, av1.z);
            ap[7] = packf2(av1.w, av1.w);
#pragma unroll
            for (int i = 0; i < 8; i++)
#pragma unroll
                for (int j = 0; j < 4; j++) fma2(acc[i][j], ap[i], bp[j], acc[i][j]);
        }
        if (k0 < 240)
            gemm_sts(tr, As[buf ^ 1], Bs[buf ^ 1], tid);
        __syncthreads();
        buf ^= 1;
    }

    float as0[8], ad0[8];
    if (SCORES) {
#pragma unroll
        for (int j = 0; j < 8; j++) {
            as0[j] = __ldg(a_s + n0 + tx * 8 + j);
            ad0[j] = __ldg(a_d + n0 + tx * 8 + j);
        }
    }

#pragma unroll
    for (int i = 0; i < 8; i++) {
        int r = m0 + ty * 8 + i;
        float v[8];
        unpackf2(v[0], v[1], acc[i][0]);
        unpackf2(v[2], v[3], acc[i][1]);
        unpackf2(v[4], v[5], acc[i][2]);
        unpackf2(v[6], v[7], acc[i][3]);
        if (r < M) {
            *(float4*)(C + (size_t)r * FF + n0 + tx * 8)     = make_float4(v[0], v[1], v[2], v[3]);
            *(float4*)(C + (size_t)r * FF + n0 + tx * 8 + 4) = make_float4(v[4], v[5], v[6], v[7]);
        }
        if (SCORES) {
            float ps = 0.f, pd = 0.f;
#pragma unroll
            for (int j = 0; j < 8; j++) { ps += v[j] * as0[j]; pd += v[j] * ad0[j]; }
#pragma unroll
            for (int o = 8; o > 0; o >>= 1) {
                ps += __shfl_xor_sync(0xffffffffu, ps, o);
                pd += __shfl_xor_sync(0xffffffffu, pd, o);
            }
            if ((tid & 15) == 0 && r < M) {
                atomicAdd(hs + r, ps);
                atomicAdd(hd + r, pd);
            }
        }
    }
}

// dual GCN GEMM: blocks [0,GB) do (A0,W0)->C rows 0.., blocks [GB,2GB) do (A1,W1)->C rows M..
__global__ void __launch_bounds__(256) k_gemm_dual(const float* __restrict__ A0,
                                                   const float* __restrict__ W0,
                                                   const float* __restrict__ A1,
                                                   const float* __restrict__ W1,
                                                   float* __restrict__ C, int M, int GB) {
    __shared__ float As[2][16][128];
    __shared__ float Bs[2][16][128];
    int bx = blockIdx.x;
    bool second = bx >= GB;
    const float* A = second ? A1 : A0;
    const float* W = second ? W1 : W0;
    float* Cp = second ? (C + (size_t)M * FF) : C;
    int m0 = (second ? bx - GB : bx) * 128;
    int n0 = blockIdx.y * 128;
    gemm_body<false>(A, W, Cp, M, m0, n0, nullptr, nullptr, nullptr, nullptr, As, Bs);
}

template<bool SCORES>
__global__ void __launch_bounds__(256) k_gemm256(const float* __restrict__ A,
                                                 const float* __restrict__ W,
                                                 float* __restrict__ C, int M,
                                                 const float* __restrict__ a_s,
                                                 const float* __restrict__ a_d,
                                                 float* __restrict__ hs,
                                                 float* __restrict__ hd) {
    __shared__ float As[2][16][128];
    __shared__ float Bs[2][16][128];
    gemm_body<SCORES>(A, W, C, M, blockIdx.x * 128, blockIdx.y * 128,
                      a_s, a_d, hs, hd, As, Bs);
}

// ---------------- GCN gather: warp per node (combined graph) ----------------
__global__ void k_gcn_gather(const int* __restrict__ off, const int* __restrict__ csr,
                             const float* __restrict__ h, float* __restrict__ out,
                             const float* __restrict__ dinv,
                             const float* __restrict__ bab, const float* __restrict__ bag,
                             int n, int nsplit) {
    int w = (blockIdx.x * blockDim.x + threadIdx.x) >> 5;
    int lane = threadIdx.x & 31;
    if (w >= n) return;
    int e0 = off[w], e1 = off[w + 1];
    float dv = dinv[w];
    float4 a0 = make_float4(0.f, 0.f, 0.f, 0.f);
    float4 a1 = make_float4(0.f, 0.f, 0.f, 0.f);
    for (int base = e0; base < e1; base += 32) {
        int e = base + lane;
        int idx = (e < e1) ? csr[e] : 0;
        float wv = (e < e1) ? dinv[idx] : 0.f;
        int cnt = min(32, e1 - base);
        for (int k = 0; k < cnt; k++) {
            int s = __shfl_sync(0xffffffffu, idx, k);
            float ws = __shfl_sync(0xffffffffu, wv, k);
            const float4* hp = (const float4*)(h + (size_t)s * FF) + lane;
            float4 v0 = hp[0];
            float4 v1 = hp[32];
            a0.x += v0.x * ws; a0.y += v0.y * ws; a0.z += v0.z * ws; a0.w += v0.w * ws;
            a1.x += v1.x * ws; a1.y += v1.y * ws; a1.z += v1.z * ws; a1.w += v1.w * ws;
        }
    }
    {
        const float4* hp = (const float4*)(h + (size_t)w * FF) + lane;
        float4 v0 = hp[0], v1 = hp[32];
        a0.x += v0.x * dv; a0.y += v0.y * dv; a0.z += v0.z * dv; a0.w += v0.w * dv;
        a1.x += v1.x * dv; a1.y += v1.y * dv; a1.z += v1.z * dv; a1.w += v1.w * dv;
    }
    const float* b = (w < nsplit) ? bab : bag;
    float4 b0 = *((const float4*)b + lane);
    float4 b1 = *((const float4*)b + lane + 32);
    float4 o0 = make_float4(a0.x * dv + b0.x, a0.y * dv + b0.y, a0.z * dv + b0.z, a0.w * dv + b0.w);
    float4 o1 = make_float4(a1.x * dv + b1.x, a1.y * dv + b1.y, a1.z * dv + b1.z, a1.w * dv + b1.w);
    float4* op = (float4*)(out + (size_t)w * FF) + lane;
    op[0] = o0;
    op[32] = o1;
}

// ---------------- BN ----------------
__global__ void k_stats4(const float* __restrict__ p0, const float* __restrict__ p1,
                         const float* __restrict__ p2, const float* __restrict__ p3,
                         int nrows, float* __restrict__ sum, float* __restrict__ sq) {
    int seg = blockIdx.y;
    const float* X = (seg == 0) ? p0 : (seg == 1) ? p1 : (seg == 2) ? p2 : p3;
    int c = threadIdx.x;
    float s = 0.f, q = 0.f;
    for (int r = blockIdx.x; r < nrows; r += gridDim.x) {
        float v = X[(size_t)r * FF + c];
        s += v; q += v * v;
    }
    atomicAdd(&sum[seg * 256 + c], s);
    atomicAdd(&sq[seg * 256 + c], q);
}

__global__ void k_finalize(const float* __restrict__ sum, const float* __restrict__ sq,
                           float* __restrict__ mu, float* __restrict__ rstd, int n, int cnt) {
    int i = blockIdx.x * blockDim.x + threadIdx.x;
    if (i >= cnt) return;
    float m = sum[i] / n;
    mu[i] = m;
    rstd[i] = rsqrtf(sq[i] / n - m * m + EPS);
}

__global__ void k_bnrelu2(const float* __restrict__ X, float* __restrict__ Y,
                          const float* __restrict__ mu, const float* __restrict__ rstd,
                          const float* __restrict__ ga, const float* __restrict__ ba,
                          const float* __restrict__ gb, const float* __restrict__ bb,
                          int n, int nsplit) {
    size_t idx = (size_t)blockIdx.x * blockDim.x + threadIdx.x;
    if (idx >= (size_t)n * FF) return;
    int node = (int)(idx >> 8), c = (int)(idx & 255);
    bool lo = node < nsplit;
    int mc = lo ? c : c + 256;
    const float* g = lo ? ga : gb;
    const float* b = lo ? ba : bb;
    float v = (X[idx] - mu[mc]) * rstd[mc] * g[c] + b[c];
    Y[idx] = fmaxf(v, 0.f);
}

// ---------------- fused GAT per node (optional output relu) ----------------
__global__ void k_gat_node(const int* __restrict__ off, const int* __restrict__ csr,
                           const float* __restrict__ h, float* __restrict__ out,
                           const float* __restrict__ hs, const float* __restrict__ hd,
                           const float* __restrict__ b, int n, int relu_out) {
    int w = (blockIdx.x * blockDim.x + threadIdx.x) >> 5;
    int lane = threadIdx.x & 31;
    if (w >= n) return;
    int e0 = off[w], e1 = off[w + 1];
    float hdn = hd[w];
    float self_e = lrelu(hs[w] + hdn);

    float m = (lane == 0) ? self_e : NINF;
    float s = (lane == 0) ? 1.f : 0.f;
    for (int e = e0 + lane; e < e1; e += 32) {
        float v = lrelu(hs[csr[e]] + hdn);
        if (v > m) { s = s * __expf(m - v) + 1.f; m = v; }
        else       { s += __expf(v - m); }
    }
#pragma unroll
    for (int o = 16; o > 0; o >>= 1) {
        float mo = __shfl_xor_sync(0xffffffffu, m, o);
        float so = __shfl_xor_sync(0xffffffffu, s, o);
        float mn = fmaxf(m, mo);
        s = s * __expf(m - mn) + so * __expf(mo - mn);
        m = mn;
    }
    float inv = 1.f / s;

    float4 a0, a1;
    {
        float sa = __expf(self_e - m) * inv;
        const float4* hp = (const float4*)(h + (size_t)w * FF) + lane;
        float4 v0 = hp[0], v1 = hp[32];
        a0 = make_float4(v0.x * sa, v0.y * sa, v0.z * sa, v0.w * sa);
        a1 = make_float4(v1.x * sa, v1.y * sa, v1.z * sa, v1.w * sa);
    }
    for (int base = e0; base < e1; base += 32) {
        int e = base + lane;
        int idx = (e < e1) ? csr[e] : 0;
        float al = 0.f;
        if (e < e1) al = __expf(lrelu(hs[idx] + hdn) - m) * inv;
        int cnt = min(32, e1 - base);
        for (int k = 0; k < cnt; k++) {
            int sn = __shfl_sync(0xffffffffu, idx, k);
            float av = __shfl_sync(0xffffffffu, al, k);
            const float4* hp = (const float4*)(h + (size_t)sn * FF) + lane;
            float4 v0 = hp[0];
            float4 v1 = hp[32];
            a0.x += v0.x * av; a0.y += v0.y * av; a0.z += v0.z * av; a0.w += v0.w * av;
            a1.x += v1.x * av; a1.y += v1.y * av; a1.z += v1.z * av; a1.w += v1.w * av;
        }
    }
    float4 b0 = *((const float4*)b + lane);
    float4 b1 = *((const float4*)b + lane + 32);
    a0.x += b0.x; a0.y += b0.y; a0.z += b0.z; a0.w += b0.w;
    a1.x += b1.x; a1.y += b1.y; a1.z += b1.z; a1.w += b1.w;
    if (relu_out) {
        a0.x = fmaxf(a0.x, 0.f); a0.y = fmaxf(a0.y, 0.f);
        a0.z = fmaxf(a0.z, 0.f); a0.w = fmaxf(a0.w, 0.f);
        a1.x = fmaxf(a1.x, 0.f); a1.y = fmaxf(a1.y, 0.f);
        a1.z = fmaxf(a1.z, 0.f); a1.w = fmaxf(a1.w, 0.f);
    }
    float4* op = (float4*)(out + (size_t)w * FF) + lane;
    op[0] = a0;
    op[32] = a1;
}

// ---------------- final (merged both halves) ----------------
__global__ void k_final2(const float* __restrict__ Xp, const float* __restrict__ Hp,
                         const float* __restrict__ mu, const float* __restrict__ rstd,
                         const float* __restrict__ ga, const float* __restrict__ ba,
                         const float* __restrict__ Wa, const float* __restrict__ bfa,
                         const float* __restrict__ gb, const float* __restrict__ bb,
                         const float* __restrict__ Wb, const float* __restrict__ bfb,
                         float* __restrict__ out, int n, int nsplit) {
    int w = (blockIdx.x * blockDim.x + threadIdx.x) >> 5;
    int lane = threadIdx.x & 31;
    if (w >= n) return;
    bool lo = w < nsplit;
    int muoff = lo ? 0 : 512;
    const float* g   = lo ? ga  : gb;
    const float* b   = lo ? ba  : bb;
    const float* Wfc = lo ? Wa  : Wb;
    float bias = lo ? bfa[0] : bfb[0];
    float acc = 0.f;
#pragma unroll
    for (int j = 0; j < 16; j++) {
        int c = j * 32 + lane;
        float v = (c < FF) ? Xp[(size_t)w * FF + c] : Hp[(size_t)w * FF + (c - FF)];
        v = (v - mu[muoff + c]) * rstd[muoff + c] * g[c] + b[c];
        v = fmaxf(v, 0.f);
        acc += v * __ldg(Wfc + c);
    }
#pragma unroll
    for (int off = 16; off > 0; off >>= 1) acc += __shfl_down_sync(0xffffffffu, acc, off);
    if (lane == 0) out[w] = acc + bias;
}

// ---------------- host orchestration ----------------
static void gat_layer(const float* xin, const float* W, const float* a_s,
                      const float* a_d, const float* b, float* hbuf, float* outbuf,
                      const int* off, const int* csr, float* sc, int relu_out) {
    k_fill<<<(2 * NTOT + 255) / 256, 256>>>(sc, 0.f, 2 * NTOT);
    dim3 gg((NTOT + 127) / 128, 2);
    k_gemm256<true><<<gg, 256>>>(xin, W, hbuf, NTOT, a_s, a_d, sc, sc + NTOT);
    k_gat_node<<<(NTOT * 32 + 255) / 256, 256>>>(off, csr, hbuf, outbuf, sc, sc + NTOT,
                                                 b, NTOT, relu_out);
}

extern "C" void kernel_launch(void* const* d_in, const int* in_sizes, int n_in,
                              void* d_out, int out_size) {
    const float* x_ab   = (const float*)d_in[0];
    const float* x_ag   = (const float*)d_in[1];
    const float* W_gcn  = (const float*)d_in[2];
    const float* b_gcn  = (const float*)d_in[3];
    const float* g1     = (const float*)d_in[4];
    const float* be1    = (const float*)d_in[5];
    const float* W_aggcn= (const float*)d_in[6];
    const float* b_aggcn= (const float*)d_in[7];
    const float* ag_g1  = (const float*)d_in[8];
    const float* ag_be1 = (const float*)d_in[9];
    const float* W_gat  = (const float*)d_in[10];
    const float* a_src  = (const float*)d_in[11];
    const float* a_dst  = (const float*)d_in[12];
    const float* b_gat  = (const float*)d_in[13];
    const float* W_gat2 = (const float*)d_in[14];
    const float* a_src2 = (const float*)d_in[15];
    const float* a_dst2 = (const float*)d_in[16];
    const float* b_gat2 = (const float*)d_in[17];
    const float* ag_g2  = (const float*)d_in[18];
    const float* ag_be2 = (const float*)d_in[19];
    const float* W_agfc = (const float*)d_in[20];
    const float* b_agfc = (const float*)d_in[21];
    const float* g2     = (const float*)d_in[22];
    const float* be2    = (const float*)d_in[23];
    const float* W_fc   = (const float*)d_in[24];
    const float* b_fc   = (const float*)d_in[25];
    const int* e_ab     = (const int*)d_in[26];
    const int* e_ag     = (const int*)d_in[27];
    const int* e_d      = (const int*)d_in[28];
    float* out = (float*)d_out;

    float *pX, *pA, *pB, *pdinv, *psc, *pss, *pmu, *prstd;
    int *pdegi, *pcur, *poff_g, *poff_d, *pcsr_g, *pcsr_d, *ppart;
    cudaGetSymbolAddress((void**)&pX, g_X);
    cudaGetSymbolAddress((void**)&pA, g_A);
    cudaGetSymbolAddress((void**)&pB, g_B);
    cudaGetSymbolAddress((void**)&pdinv, g_dinv);
    cudaGetSymbolAddress((void**)&psc, g_sc);
    cudaGetSymbolAddress((void**)&pss, g_sumsq);
    cudaGetSymbolAddress((void**)&pmu, g_mu);
    cudaGetSymbolAddress((void**)&prstd, g_rstd);
    cudaGetSymbolAddress((void**)&pdegi, g_degi);
    cudaGetSymbolAddress((void**)&pcur, g_cur);
    cudaGetSymbolAddress((void**)&poff_g, g_off_g);
    cudaGetSymbolAddress((void**)&poff_d, g_off_d);
    cudaGetSymbolAddress((void**)&pcsr_g, g_csr_g);
    cudaGetSymbolAddress((void**)&pcsr_d, g_csr_d);
    cudaGetSymbolAddress((void**)&ppart, g_partials);
    float* psum = pss;
    float* psq  = pss + 1024;

    const int* eab_src = e_ab;           const int* eab_dst = e_ab + EAB;
    const int* eag_src = e_ag;           const int* eag_dst = e_ag + EAG;
    const int* ed_src  = e_d;            const int* ed_dst  = e_d + ED;

    const int NB_TOT = (NTOT + SCAN_CHUNK - 1) / SCAN_CHUNK;   // 40
    const int GAB = (NAB + 127) / 128;                          // 157

    // ---- launches 0-2 ----
    k_filli<<<(NTOT + 255) / 256, 256>>>(pdegi, 0, NTOT);                       // 0
    k_deg2<<<(EAB + EAG + 255) / 256, 256>>>(eab_dst, EAB, eag_dst, EAG,
                                             pdegi, NAB);                       // 1
    k_dinv<<<(NTOT + 255) / 256, 256>>>(pdegi, pdinv, NTOT);                    // 2
    // ---- launch 3: merged dual GCN GEMM (profiled by ncu) ----
    {
        dim3 gd(2 * GAB, 2);
        k_gemm_dual<<<gd, 256>>>(x_ab, W_gcn, x_ag, W_aggcn, pB, NAB, GAB);     // 3
    }

    // ---- combined GCN CSR over NTOT ----
    k_scan1<<<NB_TOT, SCAN_T>>>(pdegi, NTOT, ppart);
    k_scan2<<<1, 64>>>(ppart, NB_TOT, poff_g, NTOT);
    k_scan3<<<NB_TOT, SCAN_T>>>(pdegi, NTOT, ppart, poff_g, pcur);
    k_scatter2<<<(EAB + EAG + 255) / 256, 256>>>(eab_src, eab_dst, EAB,
                                                 eag_src, eag_dst, EAG,
                                                 pcur, pcsr_g, NAB);

    // ---- GCN aggregate (gather) into g_A ----
    k_gcn_gather<<<(NTOT * 32 + 255) / 256, 256>>>(poff_g, pcsr_g, pB, pA, pdinv,
                                                   b_gcn, b_aggcn, NTOT, NAB);

    // ---- CSR build: d graph ----
    k_filli<<<(NTOT + 255) / 256, 256>>>(pdegi, 0, NTOT);
    k_deg<<<(ED + 255) / 256, 256>>>(ed_dst, ED, pdegi);
    k_scan1<<<NB_TOT, SCAN_T>>>(pdegi, NTOT, ppart);
    k_scan2<<<1, 64>>>(ppart, NB_TOT, poff_d, NTOT);
    k_scan3<<<NB_TOT, SCAN_T>>>(pdegi, NTOT, ppart, poff_d, pcur);
    k_scatter<<<(ED + 255) / 256, 256>>>(ed_src, ed_dst, ED, pcur, pcsr_d, 0, 0);

    // ---- BN1 + relu -> g_X ----
    k_fill<<<8, 256>>>(pss, 0.f, 2048);
    {
        dim3 gs(96, 2);
        k_stats4<<<gs, 256>>>(pA, pA + (size_t)NAB * FF, nullptr, nullptr, NAB, psum, psq);
    }
    k_finalize<<<2, 256>>>(psum, psq, pmu, prstd, NAB, 512);
    k_bnrelu2<<<((size_t)NTOT * FF + 255) / 256, 256>>>(pA, pX, pmu, prstd,
                                                        g1, be1, ag_g1, ag_be1, NTOT, NAB);

    // ---- GAT1 (relu fused into gat_node output) ; GAT2 ----
    gat_layer(pX, W_gat,  a_src,  a_dst,  b_gat,  pB, pA, poff_d, pcsr_d, psc, 1);
    gat_layer(pA, W_gat2, a_src2, a_dst2, b_gat2, pB, pA, poff_d, pcsr_d, psc, 0);

    // ---- final BN stats over concat halves ----
    k_fill<<<8, 256>>>(pss, 0.f, 2048);
    {
        dim3 gs(96, 4);
        k_stats4<<<gs, 256>>>(pA, pX, pA + (size_t)NAB * FF, pX + (size_t)NAB * FF,
                              NAB, psum, psq);
    }
    k_finalize<<<4, 256>>>(psum, psq, pmu, prstd, NAB, 1024);

    // ---- final outputs (merged) ----
    k_final2<<<(NTOT * 32 + 255) / 256, 256>>>(pA, pX, pmu, prstd,
                                               g2, be2, W_fc, b_fc,
                                               ag_g2, ag_be2, W_agfc, b_agfc,
                                               out, NTOT, NAB);
}